// round 13
// baseline (speedup 1.0000x reference)
#include <cuda_runtime.h>
#include <cuda_bf16.h>
#include <math.h>
#include <stdint.h>

#define MODEL_DIM 256
#define NUM_HEAD  8
#define HEAD_DIM  32
#define SEQ       128
#define BATCH     2
#define ROWS      (BATCH * SEQ * SEQ)   /* 32768 */
#define QKV_DIM   768
#define SCALE     0.17677669529663687f  /* 32^-0.5 */
#define LN_EPS    1e-5f
#define MASK_BIAS -1000000000.0f
#define MASK_N    (BATCH * SEQ * SEQ)

// -------- scratch (static device globals; no runtime allocation) --------
__device__ __nv_bfloat16 g_qkvhi[(size_t)ROWS * QKV_DIM];  // 48 MB (rotary+scale applied)
__device__ __nv_bfloat16 g_qkvlo[(size_t)ROWS * QKV_DIM];  // 48 MB
__device__ __nv_bfloat16 g_xhi[(size_t)ROWS * MODEL_DIM];
__device__ __nv_bfloat16 g_xlo[(size_t)ROWS * MODEL_DIM];
__device__ __nv_bfloat16 g_ohi[(size_t)ROWS * MODEL_DIM];
__device__ __nv_bfloat16 g_olo[(size_t)ROWS * MODEL_DIM];
__device__ __nv_bfloat16 g_whi[QKV_DIM * MODEL_DIM];
__device__ __nv_bfloat16 g_wlo[QKV_DIM * MODEL_DIM];
__device__ __nv_bfloat16 g_wohi[MODEL_DIM * MODEL_DIM];
__device__ __nv_bfloat16 g_wolo[MODEL_DIM * MODEL_DIM];
__device__ unsigned g_mask_is_u8;

__device__ __forceinline__ uint32_t smem_u32(const void* p) {
    uint32_t a;
    asm("{ .reg .u64 t; cvta.to.shared.u64 t, %1; cvt.u32.u64 %0, t; }" : "=r"(a) : "l"(p));
    return a;
}

#define CP_ASYNC16(saddr, gptr) \
    asm volatile("cp.async.cg.shared.global [%0], [%1], 16;" :: "r"(saddr), "l"(gptr))
#define CP_COMMIT() asm volatile("cp.async.commit_group;" ::: "memory")
#define CP_WAIT(n)  asm volatile("cp.async.wait_group %0;" :: "n"(n) : "memory")

#define LDMATRIX_X4(r0, r1, r2, r3, addr) \
    asm volatile("ldmatrix.sync.aligned.m8n8.x4.shared.b16 {%0,%1,%2,%3}, [%4];" \
                 : "=r"(r0), "=r"(r1), "=r"(r2), "=r"(r3) : "r"(addr))

#define LDMATRIX_X4_T(r0, r1, r2, r3, addr) \
    asm volatile("ldmatrix.sync.aligned.m8n8.x4.trans.shared.b16 {%0,%1,%2,%3}, [%4];" \
                 : "=r"(r0), "=r"(r1), "=r"(r2), "=r"(r3) : "r"(addr))

#define MMA_BF16(d, a, b) \
    asm volatile("mma.sync.aligned.m16n8k16.row.col.f32.bf16.bf16.f32 " \
                 "{%0,%1,%2,%3}, {%4,%5,%6,%7}, {%8,%9}, {%0,%1,%2,%3};" \
                 : "+f"((d)[0]), "+f"((d)[1]), "+f"((d)[2]), "+f"((d)[3]) \
                 : "r"((a)[0]), "r"((a)[1]), "r"((a)[2]), "r"((a)[3]), \
                   "r"((b)[0]), "r"((b)[1]))

// rotary on an (even, odd) channel pair; pi in [0,16)
__device__ __forceinline__ void rot_pair(float& a, float& b, int pi, int xco, int yco) {
    int j   = pi & 7;
    int pos = (pi < 8) ? xco : yco;
    float invf = exp2f(-(float)j * 1.6609640474436813f);
    float t    = (float)pos * (2.0f / 127.0f) - 1.0f;
    float f    = t * invf;
    float c, s;
    __sincosf(f, &s, &c);
    float na = a * c - b * s;
    b = b * c + a * s;
    a = na;
}

// ------------------------------------------------------------------
// K0: detect mask element width (word widenings of 0/1 have byte i%4==1 zero)
// ------------------------------------------------------------------
__global__ void mask_detect_kernel(const unsigned char* __restrict__ m) {
    __shared__ int any;
    if (threadIdx.x == 0) any = 0;
    __syncthreads();
    int found = 0;
    for (int i = threadIdx.x; i < MASK_N / 4; i += blockDim.x)
        if (m[i * 4 + 1]) found = 1;
    if (found) atomicOr(&any, 1);
    __syncthreads();
    if (threadIdx.x == 0) g_mask_is_u8 = (unsigned)any;
}

// ------------------------------------------------------------------
// K1: fused LayerNorm + split-bf16 conversion. One warp per row of 256.
// ------------------------------------------------------------------
__global__ __launch_bounds__(256) void ln_conv_kernel(const float* __restrict__ x,
                                                      const float* __restrict__ gamma,
                                                      const float* __restrict__ beta) {
    int row  = blockIdx.x * 8 + threadIdx.y;
    int lane = threadIdx.x;
    const float* xr = x + (size_t)row * MODEL_DIM;
    float4 v[2];
    float s = 0.f, s2 = 0.f;
#pragma unroll
    for (int i = 0; i < 2; i++) {
        v[i] = reinterpret_cast<const float4*>(xr)[lane + i * 32];
        s  += v[i].x + v[i].y + v[i].z + v[i].w;
        s2 += v[i].x * v[i].x + v[i].y * v[i].y + v[i].z * v[i].z + v[i].w * v[i].w;
    }
#pragma unroll
    for (int o = 16; o; o >>= 1) {
        s  += __shfl_xor_sync(0xffffffffu, s, o);
        s2 += __shfl_xor_sync(0xffffffffu, s2, o);
    }
    float mu  = s * (1.0f / MODEL_DIM);
    float var = s2 * (1.0f / MODEL_DIM) - mu * mu;
    float rs  = rsqrtf(var + LN_EPS);
#pragma unroll
    for (int i = 0; i < 2; i++) {
        int c0 = (lane + i * 32) * 4;
        float y[4] = {v[i].x, v[i].y, v[i].z, v[i].w};
#pragma unroll
        for (int j = 0; j < 4; j++)
            y[j] = (y[j] - mu) * rs * gamma[c0 + j] + beta[c0 + j];
        __nv_bfloat16 hi[4], lo[4];
#pragma unroll
        for (int j = 0; j < 4; j++) {
            hi[j] = __float2bfloat16(y[j]);
            lo[j] = __float2bfloat16(y[j] - __bfloat162float(hi[j]));
        }
        size_t o0 = (size_t)row * MODEL_DIM + c0;
        *(__nv_bfloat162*)(g_xhi + o0)     = __nv_bfloat162(hi[0], hi[1]);
        *(__nv_bfloat162*)(g_xhi + o0 + 2) = __nv_bfloat162(hi[2], hi[3]);
        *(__nv_bfloat162*)(g_xlo + o0)     = __nv_bfloat162(lo[0], lo[1]);
        *(__nv_bfloat162*)(g_xlo + o0 + 2) = __nv_bfloat162(lo[2], lo[3]);
    }
}

// ------------------------------------------------------------------
// generic fp32 -> split bf16 conversion (weights)
// ------------------------------------------------------------------
__global__ __launch_bounds__(256) void conv_kernel(const float* __restrict__ src,
                                                   __nv_bfloat16* __restrict__ hi,
                                                   __nv_bfloat16* __restrict__ lo, int n4) {
    int i = blockIdx.x * blockDim.x + threadIdx.x;
    if (i >= n4) return;
    float4 v = ((const float4*)src)[i];
    float y[4] = {v.x, v.y, v.z, v.w};
    __nv_bfloat16 h[4], l[4];
#pragma unroll
    for (int j = 0; j < 4; j++) {
        h[j] = __float2bfloat16(y[j]);
        l[j] = __float2bfloat16(y[j] - __bfloat162float(h[j]));
    }
    size_t o0 = (size_t)i * 4;
    *(__nv_bfloat162*)(hi + o0)     = __nv_bfloat162(h[0], h[1]);
    *(__nv_bfloat162*)(hi + o0 + 2) = __nv_bfloat162(h[2], h[3]);
    *(__nv_bfloat162*)(lo + o0)     = __nv_bfloat162(l[0], l[1]);
    *(__nv_bfloat162*)(lo + o0 + 2) = __nv_bfloat162(l[2], l[3]);
}

// ------------------------------------------------------------------
// K2/K5: HMMA split-bf16 GEMM, 2-stage cp.async pipeline.
// QKV_EPI=0: write fp32 C. QKV_EPI=1: apply SCALE (cols<256) + rotary
// (q cols<32, k cols 256..287) and write split-bf16 to Chi/Clo.
// ------------------------------------------------------------------
#define KCH       32
#define NCHUNK    8
#define PITCH     40
#define BUF_B     (128 * PITCH * 2)
#define STAGE_B   (4 * BUF_B)
#define GSM_TOTAL (2 * STAGE_B)

template <int QKV_EPI>
__global__ __launch_bounds__(256) void mma_gemm_kernel(
    const __nv_bfloat16* __restrict__ Ahi, const __nv_bfloat16* __restrict__ Alo,
    const __nv_bfloat16* __restrict__ Bhi, const __nv_bfloat16* __restrict__ Blo,
    float* __restrict__ C, __nv_bfloat16* __restrict__ Chi,
    __nv_bfloat16* __restrict__ Clo, int N) {
    extern __shared__ char smem[];
    uint32_t sbase = smem_u32(smem);
    int tid  = threadIdx.x;
    int lane = tid & 31;
    int wid  = tid >> 5;
    int wm   = wid >> 1;
    int wn   = wid & 1;
    int m0   = blockIdx.y * 128;
    int n0   = blockIdx.x * 128;

    float acc[2][8][4];
#pragma unroll
    for (int mt = 0; mt < 2; mt++)
#pragma unroll
        for (int nt = 0; nt < 8; nt++)
#pragma unroll
            for (int j = 0; j < 4; j++) acc[mt][nt][j] = 0.f;

    const uint4* gsrc[4] = {
        (const uint4*)(Ahi + (size_t)m0 * MODEL_DIM),
        (const uint4*)(Alo + (size_t)m0 * MODEL_DIM),
        (const uint4*)(Bhi + (size_t)n0 * MODEL_DIM),
        (const uint4*)(Blo + (size_t)n0 * MODEL_DIM)};

#define LOAD_CHUNK(ch, st)                                                        \
    do {                                                                          \
        uint32_t stb = sbase + (st) * STAGE_B;                                    \
        _Pragma("unroll")                                                         \
        for (int it = 0; it < 8; it++) {                                          \
            int idx = it * 256 + tid;                                             \
            int b = idx >> 9, r = (idx >> 2) & 127, c = idx & 3;                  \
            CP_ASYNC16(stb + b * BUF_B + r * (PITCH * 2) + c * 16,                \
                       (const void*)(gsrc[b] + (ch) * 4 + (size_t)r * 32 + c));   \
        }                                                                         \
        CP_COMMIT();                                                              \
    } while (0)

    int a_row_l = lane & 15;
    int a_col_l = (lane >> 4) << 3;
    int b_row_l = (lane & 7) + ((lane >> 4) & 1) * 8;
    int b_col_l = ((lane >> 3) & 1) << 3;

    LOAD_CHUNK(0, 0);

    for (int ch = 0; ch < NCHUNK; ch++) {
        int st = ch & 1;
        if (ch + 1 < NCHUNK) {
            LOAD_CHUNK(ch + 1, st ^ 1);
            CP_WAIT(1);
        } else {
            CP_WAIT(0);
        }
        __syncthreads();

        uint32_t sA_hi = sbase + st * STAGE_B;
        uint32_t sA_lo = sA_hi + BUF_B;
        uint32_t sB_hi = sA_hi + 2 * BUF_B;
        uint32_t sB_lo = sA_hi + 3 * BUF_B;

#pragma unroll
        for (int ks = 0; ks < 2; ks++) {
            int k = ks * 16;
            uint32_t ahi[2][4], alo[2][4], bhi[8][2], blo[8][2];
#pragma unroll
            for (int mt = 0; mt < 2; mt++) {
                uint32_t off = (uint32_t)((wm * 32 + mt * 16 + a_row_l) * (PITCH * 2) +
                                          (k + a_col_l) * 2);
                LDMATRIX_X4(ahi[mt][0], ahi[mt][1], ahi[mt][2], ahi[mt][3], sA_hi + off);
                LDMATRIX_X4(alo[mt][0], alo[mt][1], alo[mt][2], alo[mt][3], sA_lo + off);
            }
#pragma unroll
            for (int p = 0; p < 4; p++) {
                uint32_t off = (uint32_t)((wn * 64 + p * 16 + b_row_l) * (PITCH * 2) +
                                          (k + b_col_l) * 2);
                LDMATRIX_X4(bhi[2 * p][0], bhi[2 * p][1], bhi[2 * p + 1][0], bhi[2 * p + 1][1],
                            sB_hi + off);
                LDMATRIX_X4(blo[2 * p][0], blo[2 * p][1], blo[2 * p + 1][0], blo[2 * p + 1][1],
                            sB_lo + off);
            }
#pragma unroll
            for (int mt = 0; mt < 2; mt++)
#pragma unroll
                for (int nt = 0; nt < 8; nt++) {
                    MMA_BF16(acc[mt][nt], ahi[mt], bhi[nt]);
                    MMA_BF16(acc[mt][nt], ahi[mt], blo[nt]);
                    MMA_BF16(acc[mt][nt], alo[mt], bhi[nt]);
                }
        }
        __syncthreads();
    }
#undef LOAD_CHUNK

    int gid  = lane >> 2;
    int tq   = lane & 3;
    if (QKV_EPI == 0) {
#pragma unroll
        for (int mt = 0; mt < 2; mt++) {
            int row = m0 + wm * 32 + mt * 16 + gid;
#pragma unroll
            for (int nt = 0; nt < 8; nt++) {
                int col = n0 + wn * 64 + nt * 8 + tq * 2;
                *(float2*)(C + (size_t)row * N + col)       = make_float2(acc[mt][nt][0], acc[mt][nt][1]);
                *(float2*)(C + (size_t)(row + 8) * N + col) = make_float2(acc[mt][nt][2], acc[mt][nt][3]);
            }
        }
    } else {
        int xco = (m0 >> 7) & 127;  // rows in this tile share x; y = row & 127
#pragma unroll
        for (int mt = 0; mt < 2; mt++) {
            int r0 = m0 + wm * 32 + mt * 16 + gid;
            int y0 = r0 & 127;      // r0+8 stays in the same 128-row block
#pragma unroll
            for (int nt = 0; nt < 8; nt++) {
                int cg = n0 + wn * 64 + nt * 8 + tq * 2;
                float v0 = acc[mt][nt][0], v1 = acc[mt][nt][1];
                float v2 = acc[mt][nt][2], v3 = acc[mt][nt][3];
                if (cg < 256) {  // q: scale (+ rotary on cols<32)
                    v0 *= SCALE; v1 *= SCALE; v2 *= SCALE; v3 *= SCALE;
                    if (cg < 32) {
                        int pi = cg >> 1;
                        rot_pair(v0, v1, pi, xco, y0);
                        rot_pair(v2, v3, pi, xco, y0 + 8);
                    }
                } else if (cg < 288) {  // k rotary
                    int pi = (cg - 256) >> 1;
                    rot_pair(v0, v1, pi, xco, y0);
                    rot_pair(v2, v3, pi, xco, y0 + 8);
                }
                size_t off0 = (size_t)r0 * N + cg;
                size_t off1 = (size_t)(r0 + 8) * N + cg;
                __nv_bfloat16 h0 = __float2bfloat16(v0), h1 = __float2bfloat16(v1);
                __nv_bfloat16 h2 = __float2bfloat16(v2), h3 = __float2bfloat16(v3);
                *(__nv_bfloat162*)(Chi + off0) = __nv_bfloat162(h0, h1);
                *(__nv_bfloat162*)(Chi + off1) = __nv_bfloat162(h2, h3);
                *(__nv_bfloat162*)(Clo + off0) =
                    __nv_bfloat162(__float2bfloat16(v0 - __bfloat162float(h0)),
                                   __float2bfloat16(v1 - __bfloat162float(h1)));
                *(__nv_bfloat162*)(Clo + off1) =
                    __nv_bfloat162(__float2bfloat16(v2 - __bfloat162float(h2)),
                                   __float2bfloat16(v3 - __bfloat162float(h3)));
            }
        }
    }
}

// ------------------------------------------------------------------
// K4: tensorized attention per (b,x,h). 128 threads (4 warps).
// q pre-scaled + rotary applied by qkv GEMM epilogue; loader is a pure
// cp.async copy of split-bf16 tiles. S = Q K^T 3-term HMMA; register
// softmax; O = P V 3-term HMMA (ldmatrix.trans for V). Emits hi/lo bf16.
// ------------------------------------------------------------------
#define APITCH    40                       /* bf16 per smem row */
#define ATILE_B   (128 * APITCH * 2)       /* 10240 bytes */
#define ASM_TOTAL (6 * ATILE_B + 512)      /* + mask floats */

__global__ __launch_bounds__(128) void attn_mma_kernel(const void* __restrict__ mask_raw) {
    extern __shared__ char asmem[];
    uint32_t sb   = smem_u32(asmem);
    uint32_t sQhi = sb;
    uint32_t sQlo = sb + ATILE_B;
    uint32_t sKhi = sb + 2 * ATILE_B;
    uint32_t sKlo = sb + 3 * ATILE_B;
    uint32_t sVhi = sb + 4 * ATILE_B;
    uint32_t sVlo = sb + 5 * ATILE_B;
    float*   Mb   = (float*)(asmem + 6 * ATILE_B);

    int h    = blockIdx.x & 7;
    int bx   = blockIdx.x >> 3;
    int tid  = threadIdx.x;
    int lane = tid & 31;
    int w    = tid >> 5;
    size_t base = (size_t)bx * 128;

    // ---------------- loader: pure cp.async of 6 tiles (128 x 64B) ----------------
    {
#pragma unroll
        for (int it = 0; it < 24; it++) {
            int idx  = it * 128 + tid;       // 0..3071
            int tile = idx >> 9;             // 0..5: Qhi,Qlo,Khi,Klo,Vhi,Vlo
            int r    = (idx >> 2) & 127;
            int chn  = idx & 3;              // 16B chunk within 64B row
            const __nv_bfloat16* srcb = (tile & 1) ? g_qkvlo : g_qkvhi;
            const char* src = (const char*)(srcb + (base + r) * QKV_DIM +
                                            (tile >> 1) * 256 + h * HEAD_DIM) + chn * 16;
            CP_ASYNC16(sb + tile * ATILE_B + r * (APITCH * 2) + chn * 16, src);
        }
        CP_COMMIT();
        size_t mi = base + tid;
        unsigned mv = g_mask_is_u8 ? (unsigned)((const unsigned char*)mask_raw)[mi]
                                   : ((const unsigned int*)mask_raw)[mi];
        Mb[tid] = (mv != 0u) ? 1.0f : 0.0f;
        CP_WAIT(0);
    }
    __syncthreads();

    // ---------------- S = Q K^T (3-term split; SCALE pre-folded) ----------------
    uint32_t aQhi[2][2][4], aQlo[2][2][4];  // [mt][ks][4]
#pragma unroll
    for (int mt = 0; mt < 2; mt++)
#pragma unroll
        for (int ks = 0; ks < 2; ks++) {
            uint32_t off = (uint32_t)((w * 32 + mt * 16 + (lane & 15)) * (APITCH * 2) +
                                      (ks * 16 + ((lane >> 4) << 3)) * 2);
            LDMATRIX_X4(aQhi[mt][ks][0], aQhi[mt][ks][1], aQhi[mt][ks][2], aQhi[mt][ks][3],
                        sQhi + off);
            LDMATRIX_X4(aQlo[mt][ks][0], aQlo[mt][ks][1], aQlo[mt][ks][2], aQlo[mt][ks][3],
                        sQlo + off);
        }

    float c[2][16][4];
#pragma unroll
    for (int mt = 0; mt < 2; mt++)
#pragma unroll
        for (int nt = 0; nt < 16; nt++)
#pragma unroll
            for (int j = 0; j < 4; j++) c[mt][nt][j] = 0.f;

    int kb_row = (lane & 7) + ((lane >> 4) & 1) * 8;
    int kb_col = ((lane >> 3) & 1) << 3;
#pragma unroll
    for (int t = 0; t < 3; t++) {
        uint32_t sK = (t == 1) ? sKlo : sKhi;
#pragma unroll
        for (int ks = 0; ks < 2; ks++) {
            uint32_t bK[16][2];
#pragma unroll
            for (int p = 0; p < 8; p++) {
                uint32_t off = (uint32_t)((p * 16 + kb_row) * (APITCH * 2) +
                                          (ks * 16 + kb_col) * 2);
                LDMATRIX_X4(bK[2 * p][0], bK[2 * p][1], bK[2 * p + 1][0], bK[2 * p + 1][1],
                            sK + off);
            }
#pragma unroll
            for (int mt = 0; mt < 2; mt++) {
                const uint32_t* A = (t == 2) ? aQlo[mt][ks] : aQhi[mt][ks];
#pragma unroll
                for (int nt = 0; nt < 16; nt++) MMA_BF16(c[mt][nt], A, bK[nt]);
            }
        }
    }

    // ---------------- mask + softmax ----------------
#pragma unroll
    for (int mt = 0; mt < 2; mt++) {
        float m0 = -3.0e38f, m1 = -3.0e38f;
#pragma unroll
        for (int nt = 0; nt < 16; nt++) {
#pragma unroll
            for (int jc = 0; jc < 2; jc++) {
                int col = nt * 8 + (lane & 3) * 2 + jc;
                bool mk = (Mb[col] != 0.f);
                float v0 = mk ? MASK_BIAS : c[mt][nt][jc];
                float v1 = mk ? MASK_BIAS : c[mt][nt][jc + 2];
                c[mt][nt][jc]     = v0;
                c[mt][nt][jc + 2] = v1;
                m0 = fmaxf(m0, v0);
                m1 = fmaxf(m1, v1);
            }
        }
        m0 = fmaxf(m0, __shfl_xor_sync(0xffffffffu, m0, 1));
        m0 = fmaxf(m0, __shfl_xor_sync(0xffffffffu, m0, 2));
        m1 = fmaxf(m1, __shfl_xor_sync(0xffffffffu, m1, 1));
        m1 = fmaxf(m1, __shfl_xor_sync(0xffffffffu, m1, 2));
        float s0 = 0.f, s1 = 0.f;
#pragma unroll
        for (int nt = 0; nt < 16; nt++) {
#pragma unroll
            for (int jc = 0; jc < 2; jc++) {
                float p0 = __expf(c[mt][nt][jc] - m0);
                float p1 = __expf(c[mt][nt][jc + 2] - m1);
                c[mt][nt][jc]     = p0;
                c[mt][nt][jc + 2] = p1;
                s0 += p0;
                s1 += p1;
            }
        }
        s0 += __shfl_xor_sync(0xffffffffu, s0, 1);
        s0 += __shfl_xor_sync(0xffffffffu, s0, 2);
        s1 += __shfl_xor_sync(0xffffffffu, s1, 1);
        s1 += __shfl_xor_sync(0xffffffffu, s1, 2);
        float i0 = 1.0f / s0, i1 = 1.0f / s1;
#pragma unroll
        for (int nt = 0; nt < 16; nt++) {
            c[mt][nt][0] *= i0;
            c[mt][nt][1] *= i0;
            c[mt][nt][2] *= i1;
            c[mt][nt][3] *= i1;
        }
    }

    // ---------------- O = P V (3-term split) ----------------
    float o[2][4][4];
#pragma unroll
    for (int mt = 0; mt < 2; mt++)
#pragma unroll
        for (int nt = 0; nt < 4; nt++)
#pragma unroll
            for (int j = 0; j < 4; j++) o[mt][nt][j] = 0.f;

    int vb_row = (lane & 7) + ((lane >> 3) & 1) * 8;
    int vb_col = (lane >> 4) << 3;
#pragma unroll
    for (int ks = 0; ks < 8; ks++) {
        uint32_t bVhi[4][2], bVlo[4][2];
#pragma unroll
        for (int nb = 0; nb < 2; nb++) {
            uint32_t off = (uint32_t)((ks * 16 + vb_row) * (APITCH * 2) +
                                      (nb * 16 + vb_col) * 2);
            LDMATRIX_X4_T(bVhi[2 * nb][0], bVhi[2 * nb][1], bVhi[2 * nb + 1][0],
                          bVhi[2 * nb + 1][1], sVhi + off);
            LDMATRIX_X4_T(bVlo[2 * nb][0], bVlo[2 * nb][1], bVlo[2 * nb + 1][0],
                          bVlo[2 * nb + 1][1], sVlo + off);
        }
#pragma unroll
        for (int mt = 0; mt < 2; mt++) {
            uint32_t phi[4], plo[4];
#pragma unroll
            for (int half = 0; half < 2; half++) {
                const float* cc = c[mt][2 * ks + half];
#pragma unroll
                for (int pr = 0; pr < 2; pr++) {
                    float p0 = cc[pr * 2], p1 = cc[pr * 2 + 1];
                    __nv_bfloat16 h0 = __float2bfloat16(p0), h1 = __float2bfloat16(p1);
                    __nv_bfloat162 hp(h0, h1);
                    phi[half * 2 + pr] = *(uint32_t*)&hp;
                    __nv_bfloat162 lp(__float2bfloat16(p0 - __bfloat162float(h0)),
                                      __float2bfloat16(p1 - __bfloat162float(h1)));
                    plo[half * 2 + pr] = *(uint32_t*)&lp;
                }
            }
#pragma unroll
            for (int nt = 0; nt < 4; nt++) {
                MMA_BF16(o[mt][nt], phi, bVhi[nt]);
                MMA_BF16(o[mt][nt], phi, bVlo[nt]);
                MMA_BF16(o[mt][nt], plo, bVhi[nt]);
            }
        }
    }

    // ---------------- epilogue: split-bf16 store ----------------
    int gid = lane >> 2, tq = lane & 3;
#pragma unroll
    for (int mt = 0; mt < 2; mt++) {
        int row0 = w * 32 + mt * 16 + gid;
#pragma unroll
        for (int nt = 0; nt < 4; nt++) {
            int col = h * 32 + nt * 8 + tq * 2;
            size_t off0 = (base + row0) * MODEL_DIM + col;
            size_t off1 = (base + row0 + 8) * MODEL_DIM + col;
            float v0 = o[mt][nt][0], v1 = o[mt][nt][1];
            float v2 = o[mt][nt][2], v3 = o[mt][nt][3];
            __nv_bfloat16 h0 = __float2bfloat16(v0), h1 = __float2bfloat16(v1);
            __nv_bfloat16 h2 = __float2bfloat16(v2), h3 = __float2bfloat16(v3);
            *(__nv_bfloat162*)(g_ohi + off0) = __nv_bfloat162(h0, h1);
            *(__nv_bfloat162*)(g_ohi + off1) = __nv_bfloat162(h2, h3);
            *(__nv_bfloat162*)(g_olo + off0) =
                __nv_bfloat162(__float2bfloat16(v0 - __bfloat162float(h0)),
                               __float2bfloat16(v1 - __bfloat162float(h1)));
            *(__nv_bfloat162*)(g_olo + off1) =
                __nv_bfloat162(__float2bfloat16(v2 - __bfloat162float(h2)),
                               __float2bfloat16(v3 - __bfloat162float(h3)));
        }
    }
}

// ------------------------------------------------------------------
extern "C" void kernel_launch(void* const* d_in, const int* in_sizes, int n_in,
                              void* d_out, int out_size) {
    const float* pair_act  = (const float*)d_in[0];
    const void*  pair_mask = (const void*)d_in[1];
    const float* ln_gamma  = (const float*)d_in[2];
    const float* ln_beta   = (const float*)d_in[3];
    const float* Wqkv      = (const float*)d_in[4];
    const float* Wout      = (const float*)d_in[5];
    float*       out       = (float*)d_out;

    (void)in_sizes; (void)n_in; (void)out_size;

    cudaFuncSetAttribute(mma_gemm_kernel<0>, cudaFuncAttributeMaxDynamicSharedMemorySize, GSM_TOTAL);
    cudaFuncSetAttribute(mma_gemm_kernel<1>, cudaFuncAttributeMaxDynamicSharedMemorySize, GSM_TOTAL);
    cudaFuncSetAttribute(attn_mma_kernel, cudaFuncAttributeMaxDynamicSharedMemorySize, ASM_TOTAL);

    __nv_bfloat16 *xhi, *xlo, *ohi, *olo, *whi, *wlo, *wohi, *wolo, *qhi, *qlo;
    cudaGetSymbolAddress((void**)&xhi, g_xhi);
    cudaGetSymbolAddress((void**)&xlo, g_xlo);
    cudaGetSymbolAddress((void**)&ohi, g_ohi);
    cudaGetSymbolAddress((void**)&olo, g_olo);
    cudaGetSymbolAddress((void**)&whi, g_whi);
    cudaGetSymbolAddress((void**)&wlo, g_wlo);
    cudaGetSymbolAddress((void**)&wohi, g_wohi);
    cudaGetSymbolAddress((void**)&wolo, g_wolo);
    cudaGetSymbolAddress((void**)&qhi, g_qkvhi);
    cudaGetSymbolAddress((void**)&qlo, g_qkvlo);

    mask_detect_kernel<<<1, 256>>>((const unsigned char*)pair_mask);
    ln_conv_kernel<<<ROWS / 8, dim3(32, 8)>>>(pair_act, ln_gamma, ln_beta);
    conv_kernel<<<(QKV_DIM * MODEL_DIM / 4 + 255) / 256, 256>>>(Wqkv, whi, wlo, QKV_DIM * MODEL_DIM / 4);
    conv_kernel<<<(MODEL_DIM * MODEL_DIM / 4 + 255) / 256, 256>>>(Wout, wohi, wolo, MODEL_DIM * MODEL_DIM / 4);

    mma_gemm_kernel<1><<<dim3(QKV_DIM / 128, ROWS / 128), 256, GSM_TOTAL>>>(
        xhi, xlo, whi, wlo, nullptr, qhi, qlo, QKV_DIM);

    attn_mma_kernel<<<BATCH * SEQ * NUM_HEAD, 128, ASM_TOTAL>>>(pair_mask);

    mma_gemm_kernel<0><<<dim3(MODEL_DIM / 128, ROWS / 128), 256, GSM_TOTAL>>>(
        ohi, olo, wohi, wolo, out, nullptr, nullptr, MODEL_DIM);
}

// round 14
// speedup vs baseline: 1.3057x; 1.3057x over previous
#include <cuda_runtime.h>
#include <cuda_bf16.h>
#include <cuda_fp16.h>
#include <math.h>
#include <stdint.h>

#define MODEL_DIM 256
#define NUM_HEAD  8
#define HEAD_DIM  32
#define SEQ       128
#define BATCH     2
#define ROWS      (BATCH * SEQ * SEQ)   /* 32768 */
#define QKV_DIM   768
#define SCALE     0.17677669529663687f  /* 32^-0.5 */
#define LN_EPS    1e-5f
#define MASK_BIAS -1000000000.0f
#define MASK_N    (BATCH * SEQ * SEQ)

// -------- scratch (static device globals; no runtime allocation) --------
__device__ __nv_bfloat16 g_qkvhi[(size_t)ROWS * QKV_DIM];  // attention inputs (bf16 split)
__device__ __nv_bfloat16 g_qkvlo[(size_t)ROWS * QKV_DIM];
__device__ __half g_xhi[(size_t)ROWS * MODEL_DIM];         // LN(x) fp16 split
__device__ __half g_xlo[(size_t)ROWS * MODEL_DIM];
__device__ __half g_ohi[(size_t)ROWS * MODEL_DIM];         // attn out fp16 split
__device__ __half g_olo[(size_t)ROWS * MODEL_DIM];
__device__ __half g_wf[QKV_DIM * MODEL_DIM];               // Wqkv fp16
__device__ __half g_wof[MODEL_DIM * MODEL_DIM];            // Wout fp16
__device__ float  g_rotc[16 * 128];                        // rotary cos table
__device__ float  g_rots[16 * 128];                        // rotary sin table
__device__ unsigned g_mask_is_u8;

__device__ __forceinline__ uint32_t smem_u32(const void* p) {
    uint32_t a;
    asm("{ .reg .u64 t; cvta.to.shared.u64 t, %1; cvt.u32.u64 %0, t; }" : "=r"(a) : "l"(p));
    return a;
}

#define CP_ASYNC16(saddr, gptr) \
    asm volatile("cp.async.cg.shared.global [%0], [%1], 16;" :: "r"(saddr), "l"(gptr))
#define CP_COMMIT() asm volatile("cp.async.commit_group;" ::: "memory")
#define CP_WAIT(n)  asm volatile("cp.async.wait_group %0;" :: "n"(n) : "memory")

#define LDMATRIX_X4(r0, r1, r2, r3, addr) \
    asm volatile("ldmatrix.sync.aligned.m8n8.x4.shared.b16 {%0,%1,%2,%3}, [%4];" \
                 : "=r"(r0), "=r"(r1), "=r"(r2), "=r"(r3) : "r"(addr))

#define LDMATRIX_X4_T(r0, r1, r2, r3, addr) \
    asm volatile("ldmatrix.sync.aligned.m8n8.x4.trans.shared.b16 {%0,%1,%2,%3}, [%4];" \
                 : "=r"(r0), "=r"(r1), "=r"(r2), "=r"(r3) : "r"(addr))

#define MMA_BF16(d, a, b) \
    asm volatile("mma.sync.aligned.m16n8k16.row.col.f32.bf16.bf16.f32 " \
                 "{%0,%1,%2,%3}, {%4,%5,%6,%7}, {%8,%9}, {%0,%1,%2,%3};" \
                 : "+f"((d)[0]), "+f"((d)[1]), "+f"((d)[2]), "+f"((d)[3]) \
                 : "r"((a)[0]), "r"((a)[1]), "r"((a)[2]), "r"((a)[3]), \
                   "r"((b)[0]), "r"((b)[1]))

#define MMA_F16(d, a, b) \
    asm volatile("mma.sync.aligned.m16n8k16.row.col.f32.f16.f16.f32 " \
                 "{%0,%1,%2,%3}, {%4,%5,%6,%7}, {%8,%9}, {%0,%1,%2,%3};" \
                 : "+f"((d)[0]), "+f"((d)[1]), "+f"((d)[2]), "+f"((d)[3]) \
                 : "r"((a)[0]), "r"((a)[1]), "r"((a)[2]), "r"((a)[3]), \
                   "r"((b)[0]), "r"((b)[1]))

// ------------------------------------------------------------------
// K0a: detect mask element width (word widenings of 0/1 have byte i%4==1 zero)
// ------------------------------------------------------------------
__global__ void mask_detect_kernel(const unsigned char* __restrict__ m) {
    __shared__ int any;
    if (threadIdx.x == 0) any = 0;
    __syncthreads();
    int found = 0;
    for (int i = threadIdx.x; i < MASK_N / 4; i += blockDim.x)
        if (m[i * 4 + 1]) found = 1;
    if (found) atomicOr(&any, 1);
    __syncthreads();
    if (threadIdx.x == 0) g_mask_is_u8 = (unsigned)any;
}

// ------------------------------------------------------------------
// K0b: fill rotary cos/sin table: index = pi*128 + pos, pi in [0,16)
// ------------------------------------------------------------------
__global__ void rot_fill_kernel() {
    int i   = blockIdx.x * 256 + threadIdx.x;  // 0..2047
    int pi  = i >> 7;
    int pos = i & 127;
    float invf = exp2f(-(float)(pi & 7) * 1.6609640474436813f);
    float t    = (float)pos * (2.0f / 127.0f) - 1.0f;
    float f    = t * invf;
    g_rotc[i] = cosf(f);
    g_rots[i] = sinf(f);
}

// ------------------------------------------------------------------
// K1: fused LayerNorm + split-fp16 conversion. One warp per row of 256.
// ------------------------------------------------------------------
__global__ __launch_bounds__(256) void ln_conv_kernel(const float* __restrict__ x,
                                                      const float* __restrict__ gamma,
                                                      const float* __restrict__ beta) {
    int row  = blockIdx.x * 8 + threadIdx.y;
    int lane = threadIdx.x;
    const float* xr = x + (size_t)row * MODEL_DIM;
    float4 v[2];
    float s = 0.f, s2 = 0.f;
#pragma unroll
    for (int i = 0; i < 2; i++) {
        v[i] = reinterpret_cast<const float4*>(xr)[lane + i * 32];
        s  += v[i].x + v[i].y + v[i].z + v[i].w;
        s2 += v[i].x * v[i].x + v[i].y * v[i].y + v[i].z * v[i].z + v[i].w * v[i].w;
    }
#pragma unroll
    for (int o = 16; o; o >>= 1) {
        s  += __shfl_xor_sync(0xffffffffu, s, o);
        s2 += __shfl_xor_sync(0xffffffffu, s2, o);
    }
    float mu  = s * (1.0f / MODEL_DIM);
    float var = s2 * (1.0f / MODEL_DIM) - mu * mu;
    float rs  = rsqrtf(var + LN_EPS);
#pragma unroll
    for (int i = 0; i < 2; i++) {
        int c0 = (lane + i * 32) * 4;
        float y[4] = {v[i].x, v[i].y, v[i].z, v[i].w};
#pragma unroll
        for (int j = 0; j < 4; j++)
            y[j] = (y[j] - mu) * rs * gamma[c0 + j] + beta[c0 + j];
        __half hi[4], lo[4];
#pragma unroll
        for (int j = 0; j < 4; j++) {
            hi[j] = __float2half(y[j]);
            lo[j] = __float2half(y[j] - __half2float(hi[j]));
        }
        size_t o0 = (size_t)row * MODEL_DIM + c0;
        *(__half2*)(g_xhi + o0)     = __half2(hi[0], hi[1]);
        *(__half2*)(g_xhi + o0 + 2) = __half2(hi[2], hi[3]);
        *(__half2*)(g_xlo + o0)     = __half2(lo[0], lo[1]);
        *(__half2*)(g_xlo + o0 + 2) = __half2(lo[2], lo[3]);
    }
}

// ------------------------------------------------------------------
// fp32 -> single fp16 conversion (weights)
// ------------------------------------------------------------------
__global__ __launch_bounds__(256) void convf16_kernel(const float* __restrict__ src,
                                                      __half* __restrict__ dst, int n4) {
    int i = blockIdx.x * blockDim.x + threadIdx.x;
    if (i >= n4) return;
    float4 v = ((const float4*)src)[i];
    size_t o0 = (size_t)i * 4;
    *(__half2*)(dst + o0)     = __half2(__float2half(v.x), __float2half(v.y));
    *(__half2*)(dst + o0 + 2) = __half2(__float2half(v.z), __float2half(v.w));
}

// ------------------------------------------------------------------
// K2/K5: HMMA fp16 2-term GEMM, 2-stage cp.async pipeline.
// C[M,N] = (Ahi + Alo)[M,256] * Bf[N,256]^T, fp32 accum.
// QKV_EPI=0: write fp32 C. QKV_EPI=1: SCALE (cols<256) + rotary via
// table (q cols<32, k cols 256..287), write split-bf16 Chi/Clo.
// Tile 128x128, 256 thr = 8 warps (4m x 2n); K chunks of 32.
// ------------------------------------------------------------------
#define KCH       32
#define NCHUNK    8
#define PITCH     40
#define BUF_B     (128 * PITCH * 2)      /* 10240 B */
#define STAGE_B   (3 * BUF_B)            /* 30720 B: Ahi, Alo, Bf */
#define GSM_TOTAL (2 * STAGE_B)          /* 61440 B */

template <int QKV_EPI>
__global__ __launch_bounds__(256) void mma_gemm_kernel(
    const __half* __restrict__ Ahi, const __half* __restrict__ Alo,
    const __half* __restrict__ Bf,
    float* __restrict__ C, __nv_bfloat16* __restrict__ Chi,
    __nv_bfloat16* __restrict__ Clo, int N) {
    extern __shared__ char smem[];
    uint32_t sbase = smem_u32(smem);
    int tid  = threadIdx.x;
    int lane = tid & 31;
    int wid  = tid >> 5;
    int wm   = wid >> 1;
    int wn   = wid & 1;
    int m0   = blockIdx.y * 128;
    int n0   = blockIdx.x * 128;

    float acc[2][8][4];
#pragma unroll
    for (int mt = 0; mt < 2; mt++)
#pragma unroll
        for (int nt = 0; nt < 8; nt++)
#pragma unroll
            for (int j = 0; j < 4; j++) acc[mt][nt][j] = 0.f;

    const uint4* gsrc[3] = {
        (const uint4*)(Ahi + (size_t)m0 * MODEL_DIM),
        (const uint4*)(Alo + (size_t)m0 * MODEL_DIM),
        (const uint4*)(Bf + (size_t)n0 * MODEL_DIM)};

    // loader: chunk ch -> stage st. 3 buffers x 512 x 16B = 6 per thread.
#define LOAD_CHUNK(ch, st)                                                        \
    do {                                                                          \
        uint32_t stb = sbase + (st) * STAGE_B;                                    \
        _Pragma("unroll")                                                         \
        for (int it = 0; it < 6; it++) {                                          \
            int idx = it * 256 + tid;                                             \
            int b = idx >> 9, r = (idx >> 2) & 127, c = idx & 3;                  \
            CP_ASYNC16(stb + b * BUF_B + r * (PITCH * 2) + c * 16,                \
                       (const void*)(gsrc[b] + (ch) * 4 + (size_t)r * 32 + c));   \
        }                                                                         \
        CP_COMMIT();                                                              \
    } while (0)

    int a_row_l = lane & 15;
    int a_col_l = (lane >> 4) << 3;
    int b_row_l = (lane & 7) + ((lane >> 4) & 1) * 8;
    int b_col_l = ((lane >> 3) & 1) << 3;

    LOAD_CHUNK(0, 0);

    for (int ch = 0; ch < NCHUNK; ch++) {
        int st = ch & 1;
        if (ch + 1 < NCHUNK) {
            LOAD_CHUNK(ch + 1, st ^ 1);
            CP_WAIT(1);
        } else {
            CP_WAIT(0);
        }
        __syncthreads();

        uint32_t sA_hi = sbase + st * STAGE_B;
        uint32_t sA_lo = sA_hi + BUF_B;
        uint32_t sB    = sA_hi + 2 * BUF_B;

#pragma unroll
        for (int ks = 0; ks < 2; ks++) {
            int k = ks * 16;
            uint32_t ahi[2][4], alo[2][4], bf[8][2];
#pragma unroll
            for (int mt = 0; mt < 2; mt++) {
                uint32_t off = (uint32_t)((wm * 32 + mt * 16 + a_row_l) * (PITCH * 2) +
                                          (k + a_col_l) * 2);
                LDMATRIX_X4(ahi[mt][0], ahi[mt][1], ahi[mt][2], ahi[mt][3], sA_hi + off);
                LDMATRIX_X4(alo[mt][0], alo[mt][1], alo[mt][2], alo[mt][3], sA_lo + off);
            }
#pragma unroll
            for (int p = 0; p < 4; p++) {
                uint32_t off = (uint32_t)((wn * 64 + p * 16 + b_row_l) * (PITCH * 2) +
                                          (k + b_col_l) * 2);
                LDMATRIX_X4(bf[2 * p][0], bf[2 * p][1], bf[2 * p + 1][0], bf[2 * p + 1][1],
                            sB + off);
            }
#pragma unroll
            for (int mt = 0; mt < 2; mt++)
#pragma unroll
                for (int nt = 0; nt < 8; nt++) {
                    MMA_F16(acc[mt][nt], ahi[mt], bf[nt]);
                    MMA_F16(acc[mt][nt], alo[mt], bf[nt]);
                }
        }
        __syncthreads();
    }
#undef LOAD_CHUNK

    int gid  = lane >> 2;
    int tq   = lane & 3;
    if (QKV_EPI == 0) {
#pragma unroll
        for (int mt = 0; mt < 2; mt++) {
            int row = m0 + wm * 32 + mt * 16 + gid;
#pragma unroll
            for (int nt = 0; nt < 8; nt++) {
                int col = n0 + wn * 64 + nt * 8 + tq * 2;
                *(float2*)(C + (size_t)row * N + col)       = make_float2(acc[mt][nt][0], acc[mt][nt][1]);
                *(float2*)(C + (size_t)(row + 8) * N + col) = make_float2(acc[mt][nt][2], acc[mt][nt][3]);
            }
        }
    } else {
        int xco = (m0 >> 7) & 127;  // rows in this tile share x; y = row & 127
#pragma unroll
        for (int mt = 0; mt < 2; mt++) {
            int r0 = m0 + wm * 32 + mt * 16 + gid;
            int y0 = r0 & 127;
#pragma unroll
            for (int nt = 0; nt < 8; nt++) {
                int cg = n0 + wn * 64 + nt * 8 + tq * 2;
                float v0 = acc[mt][nt][0], v1 = acc[mt][nt][1];
                float v2 = acc[mt][nt][2], v3 = acc[mt][nt][3];
                int pi = -1;
                if (cg < 256) {
                    v0 *= SCALE; v1 *= SCALE; v2 *= SCALE; v3 *= SCALE;
                    if (cg < 32) pi = cg >> 1;
                } else if (cg < 288) {
                    pi = (cg - 256) >> 1;
                }
                if (pi >= 0) {
                    int i0 = pi * 128 + ((pi < 8) ? xco : y0);
                    int i1 = pi * 128 + ((pi < 8) ? xco : y0 + 8);
                    float c0 = g_rotc[i0], s0 = g_rots[i0];
                    float c1 = g_rotc[i1], s1 = g_rots[i1];
                    float n0f = v0 * c0 - v1 * s0;
                    v1 = v1 * c0 + v0 * s0; v0 = n0f;
                    float n2f = v2 * c1 - v3 * s1;
                    v3 = v3 * c1 + v2 * s1; v2 = n2f;
                }
                size_t off0 = (size_t)r0 * N + cg;
                size_t off1 = (size_t)(r0 + 8) * N + cg;
                __nv_bfloat16 h0 = __float2bfloat16(v0), h1 = __float2bfloat16(v1);
                __nv_bfloat16 h2 = __float2bfloat16(v2), h3 = __float2bfloat16(v3);
                *(__nv_bfloat162*)(Chi + off0) = __nv_bfloat162(h0, h1);
                *(__nv_bfloat162*)(Chi + off1) = __nv_bfloat162(h2, h3);
                *(__nv_bfloat162*)(Clo + off0) =
                    __nv_bfloat162(__float2bfloat16(v0 - __bfloat162float(h0)),
                                   __float2bfloat16(v1 - __bfloat162float(h1)));
                *(__nv_bfloat162*)(Clo + off1) =
                    __nv_bfloat162(__float2bfloat16(v2 - __bfloat162float(h2)),
                                   __float2bfloat16(v3 - __bfloat162float(h3)));
            }
        }
    }
}

// ------------------------------------------------------------------
// K4: tensorized attention per (b,x,h). 128 threads (4 warps).
// q pre-scaled + rotary applied upstream; loader = pure cp.async.
// S = Q K^T 3-term bf16 HMMA; register softmax; O = P V 3-term.
// Emits fp16 hi/lo to g_ohi/g_olo for the fp16 out-GEMM.
// ------------------------------------------------------------------
#define APITCH    40
#define ATILE_B   (128 * APITCH * 2)
#define ASM_TOTAL (6 * ATILE_B + 512)

__global__ __launch_bounds__(128) void attn_mma_kernel(const void* __restrict__ mask_raw) {
    extern __shared__ char asmem[];
    uint32_t sb   = smem_u32(asmem);
    uint32_t sQhi = sb;
    uint32_t sQlo = sb + ATILE_B;
    uint32_t sKhi = sb + 2 * ATILE_B;
    uint32_t sKlo = sb + 3 * ATILE_B;
    uint32_t sVhi = sb + 4 * ATILE_B;
    uint32_t sVlo = sb + 5 * ATILE_B;
    float*   Mb   = (float*)(asmem + 6 * ATILE_B);

    int h    = blockIdx.x & 7;
    int bx   = blockIdx.x >> 3;
    int tid  = threadIdx.x;
    int lane = tid & 31;
    int w    = tid >> 5;
    size_t base = (size_t)bx * 128;

    {
#pragma unroll
        for (int it = 0; it < 24; it++) {
            int idx  = it * 128 + tid;
            int tile = idx >> 9;
            int r    = (idx >> 2) & 127;
            int chn  = idx & 3;
            const __nv_bfloat16* srcb = (tile & 1) ? g_qkvlo : g_qkvhi;
            const char* src = (const char*)(srcb + (base + r) * QKV_DIM +
                                            (tile >> 1) * 256 + h * HEAD_DIM) + chn * 16;
            CP_ASYNC16(sb + tile * ATILE_B + r * (APITCH * 2) + chn * 16, src);
        }
        CP_COMMIT();
        size_t mi = base + tid;
        unsigned mv = g_mask_is_u8 ? (unsigned)((const unsigned char*)mask_raw)[mi]
                                   : ((const unsigned int*)mask_raw)[mi];
        Mb[tid] = (mv != 0u) ? 1.0f : 0.0f;
        CP_WAIT(0);
    }
    __syncthreads();

    uint32_t aQhi[2][2][4], aQlo[2][2][4];
#pragma unroll
    for (int mt = 0; mt < 2; mt++)
#pragma unroll
        for (int ks = 0; ks < 2; ks++) {
            uint32_t off = (uint32_t)((w * 32 + mt * 16 + (lane & 15)) * (APITCH * 2) +
                                      (ks * 16 + ((lane >> 4) << 3)) * 2);
            LDMATRIX_X4(aQhi[mt][ks][0], aQhi[mt][ks][1], aQhi[mt][ks][2], aQhi[mt][ks][3],
                        sQhi + off);
            LDMATRIX_X4(aQlo[mt][ks][0], aQlo[mt][ks][1], aQlo[mt][ks][2], aQlo[mt][ks][3],
                        sQlo + off);
        }

    float c[2][16][4];
#pragma unroll
    for (int mt = 0; mt < 2; mt++)
#pragma unroll
        for (int nt = 0; nt < 16; nt++)
#pragma unroll
            for (int j = 0; j < 4; j++) c[mt][nt][j] = 0.f;

    int kb_row = (lane & 7) + ((lane >> 4) & 1) * 8;
    int kb_col = ((lane >> 3) & 1) << 3;
#pragma unroll
    for (int t = 0; t < 3; t++) {
        uint32_t sK = (t == 1) ? sKlo : sKhi;
#pragma unroll
        for (int ks = 0; ks < 2; ks++) {
            uint32_t bK[16][2];
#pragma unroll
            for (int p = 0; p < 8; p++) {
                uint32_t off = (uint32_t)((p * 16 + kb_row) * (APITCH * 2) +
                                          (ks * 16 + kb_col) * 2);
                LDMATRIX_X4(bK[2 * p][0], bK[2 * p][1], bK[2 * p + 1][0], bK[2 * p + 1][1],
                            sK + off);
            }
#pragma unroll
            for (int mt = 0; mt < 2; mt++) {
                const uint32_t* A = (t == 2) ? aQlo[mt][ks] : aQhi[mt][ks];
#pragma unroll
                for (int nt = 0; nt < 16; nt++) MMA_BF16(c[mt][nt], A, bK[nt]);
            }
        }
    }

#pragma unroll
    for (int mt = 0; mt < 2; mt++) {
        float m0 = -3.0e38f, m1 = -3.0e38f;
#pragma unroll
        for (int nt = 0; nt < 16; nt++) {
#pragma unroll
            for (int jc = 0; jc < 2; jc++) {
                int col = nt * 8 + (lane & 3) * 2 + jc;
                bool mk = (Mb[col] != 0.f);
                float v0 = mk ? MASK_BIAS : c[mt][nt][jc];
                float v1 = mk ? MASK_BIAS : c[mt][nt][jc + 2];
                c[mt][nt][jc]     = v0;
                c[mt][nt][jc + 2] = v1;
                m0 = fmaxf(m0, v0);
                m1 = fmaxf(m1, v1);
            }
        }
        m0 = fmaxf(m0, __shfl_xor_sync(0xffffffffu, m0, 1));
        m0 = fmaxf(m0, __shfl_xor_sync(0xffffffffu, m0, 2));
        m1 = fmaxf(m1, __shfl_xor_sync(0xffffffffu, m1, 1));
        m1 = fmaxf(m1, __shfl_xor_sync(0xffffffffu, m1, 2));
        float s0 = 0.f, s1 = 0.f;
#pragma unroll
        for (int nt = 0; nt < 16; nt++) {
#pragma unroll
            for (int jc = 0; jc < 2; jc++) {
                float p0 = __expf(c[mt][nt][jc] - m0);
                float p1 = __expf(c[mt][nt][jc + 2] - m1);
                c[mt][nt][jc]     = p0;
                c[mt][nt][jc + 2] = p1;
                s0 += p0;
                s1 += p1;
            }
        }
        s0 += __shfl_xor_sync(0xffffffffu, s0, 1);
        s0 += __shfl_xor_sync(0xffffffffu, s0, 2);
        s1 += __shfl_xor_sync(0xffffffffu, s1, 1);
        s1 += __shfl_xor_sync(0xffffffffu, s1, 2);
        float i0 = 1.0f / s0, i1 = 1.0f / s1;
#pragma unroll
        for (int nt = 0; nt < 16; nt++) {
            c[mt][nt][0] *= i0;
            c[mt][nt][1] *= i0;
            c[mt][nt][2] *= i1;
            c[mt][nt][3] *= i1;
        }
    }

    float o[2][4][4];
#pragma unroll
    for (int mt = 0; mt < 2; mt++)
#pragma unroll
        for (int nt = 0; nt < 4; nt++)
#pragma unroll
            for (int j = 0; j < 4; j++) o[mt][nt][j] = 0.f;

    int vb_row = (lane & 7) + ((lane >> 3) & 1) * 8;
    int vb_col = (lane >> 4) << 3;
#pragma unroll
    for (int ks = 0; ks < 8; ks++) {
        uint32_t bVhi[4][2], bVlo[4][2];
#pragma unroll
        for (int nb = 0; nb < 2; nb++) {
            uint32_t off = (uint32_t)((ks * 16 + vb_row) * (APITCH * 2) +
                                      (nb * 16 + vb_col) * 2);
            LDMATRIX_X4_T(bVhi[2 * nb][0], bVhi[2 * nb][1], bVhi[2 * nb + 1][0],
                          bVhi[2 * nb + 1][1], sVhi + off);
            LDMATRIX_X4_T(bVlo[2 * nb][0], bVlo[2 * nb][1], bVlo[2 * nb + 1][0],
                          bVlo[2 * nb + 1][1], sVlo + off);
        }
#pragma unroll
        for (int mt = 0; mt < 2; mt++) {
            uint32_t phi[4], plo[4];
#pragma unroll
            for (int half = 0; half < 2; half++) {
                const float* cc = c[mt][2 * ks + half];
#pragma unroll
                for (int pr = 0; pr < 2; pr++) {
                    float p0 = cc[pr * 2], p1 = cc[pr * 2 + 1];
                    __nv_bfloat16 h0 = __float2bfloat16(p0), h1 = __float2bfloat16(p1);
                    __nv_bfloat162 hp(h0, h1);
                    phi[half * 2 + pr] = *(uint32_t*)&hp;
                    __nv_bfloat162 lp(__float2bfloat16(p0 - __bfloat162float(h0)),
                                      __float2bfloat16(p1 - __bfloat162float(h1)));
                    plo[half * 2 + pr] = *(uint32_t*)&lp;
                }
            }
#pragma unroll
            for (int nt = 0; nt < 4; nt++) {
                MMA_BF16(o[mt][nt], phi, bVhi[nt]);
                MMA_BF16(o[mt][nt], phi, bVlo[nt]);
                MMA_BF16(o[mt][nt], plo, bVhi[nt]);
            }
        }
    }

    // epilogue: split-fp16 store for the fp16 out-GEMM
    int gid = lane >> 2, tq = lane & 3;
#pragma unroll
    for (int mt = 0; mt < 2; mt++) {
        int row0 = w * 32 + mt * 16 + gid;
#pragma unroll
        for (int nt = 0; nt < 4; nt++) {
            int col = h * 32 + nt * 8 + tq * 2;
            size_t off0 = (base + row0) * MODEL_DIM + col;
            size_t off1 = (base + row0 + 8) * MODEL_DIM + col;
            float v0 = o[mt][nt][0], v1 = o[mt][nt][1];
            float v2 = o[mt][nt][2], v3 = o[mt][nt][3];
            __half h0 = __float2half(v0), h1 = __float2half(v1);
            __half h2 = __float2half(v2), h3 = __float2half(v3);
            *(__half2*)(g_ohi + off0) = __half2(h0, h1);
            *(__half2*)(g_ohi + off1) = __half2(h2, h3);
            *(__half2*)(g_olo + off0) =
                __half2(__float2half(v0 - __half2float(h0)),
                        __float2half(v1 - __half2float(h1)));
            *(__half2*)(g_olo + off1) =
                __half2(__float2half(v2 - __half2float(h2)),
                        __float2half(v3 - __half2float(h3)));
        }
    }
}

// ------------------------------------------------------------------
extern "C" void kernel_launch(void* const* d_in, const int* in_sizes, int n_in,
                              void* d_out, int out_size) {
    const float* pair_act  = (const float*)d_in[0];
    const void*  pair_mask = (const void*)d_in[1];
    const float* ln_gamma  = (const float*)d_in[2];
    const float* ln_beta   = (const float*)d_in[3];
    const float* Wqkv      = (const float*)d_in[4];
    const float* Wout      = (const float*)d_in[5];
    float*       out       = (float*)d_out;

    (void)in_sizes; (void)n_in; (void)out_size;

    cudaFuncSetAttribute(mma_gemm_kernel<0>, cudaFuncAttributeMaxDynamicSharedMemorySize, GSM_TOTAL);
    cudaFuncSetAttribute(mma_gemm_kernel<1>, cudaFuncAttributeMaxDynamicSharedMemorySize, GSM_TOTAL);
    cudaFuncSetAttribute(attn_mma_kernel, cudaFuncAttributeMaxDynamicSharedMemorySize, ASM_TOTAL);

    __half *xhi, *xlo, *ohi, *olo, *wf, *wof;
    __nv_bfloat16 *qhi, *qlo;
    cudaGetSymbolAddress((void**)&xhi, g_xhi);
    cudaGetSymbolAddress((void**)&xlo, g_xlo);
    cudaGetSymbolAddress((void**)&ohi, g_ohi);
    cudaGetSymbolAddress((void**)&olo, g_olo);
    cudaGetSymbolAddress((void**)&wf, g_wf);
    cudaGetSymbolAddress((void**)&wof, g_wof);
    cudaGetSymbolAddress((void**)&qhi, g_qkvhi);
    cudaGetSymbolAddress((void**)&qlo, g_qkvlo);

    mask_detect_kernel<<<1, 256>>>((const unsigned char*)pair_mask);
    rot_fill_kernel<<<8, 256>>>();
    ln_conv_kernel<<<ROWS / 8, dim3(32, 8)>>>(pair_act, ln_gamma, ln_beta);
    convf16_kernel<<<(QKV_DIM * MODEL_DIM / 4 + 255) / 256, 256>>>(Wqkv, wf, QKV_DIM * MODEL_DIM / 4);
    convf16_kernel<<<(MODEL_DIM * MODEL_DIM / 4 + 255) / 256, 256>>>(Wout, wof, MODEL_DIM * MODEL_DIM / 4);

    mma_gemm_kernel<1><<<dim3(QKV_DIM / 128, ROWS / 128), 256, GSM_TOTAL>>>(
        xhi, xlo, wf, nullptr, qhi, qlo, QKV_DIM);

    attn_mma_kernel<<<BATCH * SEQ * NUM_HEAD, 128, ASM_TOTAL>>>(pair_mask);

    mma_gemm_kernel<0><<<dim3(MODEL_DIM / 128, ROWS / 128), 256, GSM_TOTAL>>>(
        ohi, olo, wof, out, nullptr, nullptr, MODEL_DIM);
}

// round 15
// speedup vs baseline: 1.5415x; 1.1806x over previous
#include <cuda_runtime.h>
#include <cuda_bf16.h>
#include <cuda_fp16.h>
#include <math.h>
#include <stdint.h>

#define MODEL_DIM 256
#define NUM_HEAD  8
#define HEAD_DIM  32
#define SEQ       128
#define BATCH     2
#define ROWS      (BATCH * SEQ * SEQ)   /* 32768 */
#define QKV_DIM   768
#define SCALE     0.17677669529663687f  /* 32^-0.5 */
#define LN_EPS    1e-5f
#define MASK_BIAS -1000000000.0f
#define MASK_N    (BATCH * SEQ * SEQ)

// -------- scratch (static device globals; no runtime allocation) --------
__device__ __nv_bfloat16 g_qkvhi[(size_t)ROWS * QKV_DIM];  // attention inputs (bf16 split)
__device__ __nv_bfloat16 g_qkvlo[(size_t)ROWS * QKV_DIM];
__device__ __half g_xf[(size_t)ROWS * MODEL_DIM];          // LN(x) fp16
__device__ __half g_of[(size_t)ROWS * MODEL_DIM];          // attn out fp16
__device__ __half g_wf[QKV_DIM * MODEL_DIM];               // Wqkv fp16
__device__ __half g_wof[MODEL_DIM * MODEL_DIM];            // Wout fp16
__device__ float  g_rotc[16 * 128];                        // rotary cos table
__device__ float  g_rots[16 * 128];                        // rotary sin table
__device__ unsigned g_mask_is_u8;

__device__ __forceinline__ uint32_t smem_u32(const void* p) {
    uint32_t a;
    asm("{ .reg .u64 t; cvta.to.shared.u64 t, %1; cvt.u32.u64 %0, t; }" : "=r"(a) : "l"(p));
    return a;
}

#define CP_ASYNC16(saddr, gptr) \
    asm volatile("cp.async.cg.shared.global [%0], [%1], 16;" :: "r"(saddr), "l"(gptr))
#define CP_COMMIT() asm volatile("cp.async.commit_group;" ::: "memory")
#define CP_WAIT(n)  asm volatile("cp.async.wait_group %0;" :: "n"(n) : "memory")

#define LDMATRIX_X4(r0, r1, r2, r3, addr) \
    asm volatile("ldmatrix.sync.aligned.m8n8.x4.shared.b16 {%0,%1,%2,%3}, [%4];" \
                 : "=r"(r0), "=r"(r1), "=r"(r2), "=r"(r3) : "r"(addr))

#define LDMATRIX_X4_T(r0, r1, r2, r3, addr) \
    asm volatile("ldmatrix.sync.aligned.m8n8.x4.trans.shared.b16 {%0,%1,%2,%3}, [%4];" \
                 : "=r"(r0), "=r"(r1), "=r"(r2), "=r"(r3) : "r"(addr))

#define MMA_BF16(d, a, b) \
    asm volatile("mma.sync.aligned.m16n8k16.row.col.f32.bf16.bf16.f32 " \
                 "{%0,%1,%2,%3}, {%4,%5,%6,%7}, {%8,%9}, {%0,%1,%2,%3};" \
                 : "+f"((d)[0]), "+f"((d)[1]), "+f"((d)[2]), "+f"((d)[3]) \
                 : "r"((a)[0]), "r"((a)[1]), "r"((a)[2]), "r"((a)[3]), \
                   "r"((b)[0]), "r"((b)[1]))

#define MMA_F16(d, a, b) \
    asm volatile("mma.sync.aligned.m16n8k16.row.col.f32.f16.f16.f32 " \
                 "{%0,%1,%2,%3}, {%4,%5,%6,%7}, {%8,%9}, {%0,%1,%2,%3};" \
                 : "+f"((d)[0]), "+f"((d)[1]), "+f"((d)[2]), "+f"((d)[3]) \
                 : "r"((a)[0]), "r"((a)[1]), "r"((a)[2]), "r"((a)[3]), \
                   "r"((b)[0]), "r"((b)[1]))

// ------------------------------------------------------------------
// K0a: detect mask element width (word widenings of 0/1 have byte i%4==1 zero)
// ------------------------------------------------------------------
__global__ void mask_detect_kernel(const unsigned char* __restrict__ m) {
    __shared__ int any;
    if (threadIdx.x == 0) any = 0;
    __syncthreads();
    int found = 0;
    for (int i = threadIdx.x; i < MASK_N / 4; i += blockDim.x)
        if (m[i * 4 + 1]) found = 1;
    if (found) atomicOr(&any, 1);
    __syncthreads();
    if (threadIdx.x == 0) g_mask_is_u8 = (unsigned)any;
}

// ------------------------------------------------------------------
// K0b: fill rotary cos/sin table: index = pi*128 + pos, pi in [0,16)
// ------------------------------------------------------------------
__global__ void rot_fill_kernel() {
    int i   = blockIdx.x * 256 + threadIdx.x;  // 0..2047
    int pi  = i >> 7;
    int pos = i & 127;
    float invf = exp2f(-(float)(pi & 7) * 1.6609640474436813f);
    float t    = (float)pos * (2.0f / 127.0f) - 1.0f;
    float f    = t * invf;
    g_rotc[i] = cosf(f);
    g_rots[i] = sinf(f);
}

// ------------------------------------------------------------------
// K1: fused LayerNorm + fp16 conversion. One warp per row of 256.
// ------------------------------------------------------------------
__global__ __launch_bounds__(256) void ln_conv_kernel(const float* __restrict__ x,
                                                      const float* __restrict__ gamma,
                                                      const float* __restrict__ beta) {
    int row  = blockIdx.x * 8 + threadIdx.y;
    int lane = threadIdx.x;
    const float* xr = x + (size_t)row * MODEL_DIM;
    float4 v[2];
    float s = 0.f, s2 = 0.f;
#pragma unroll
    for (int i = 0; i < 2; i++) {
        v[i] = reinterpret_cast<const float4*>(xr)[lane + i * 32];
        s  += v[i].x + v[i].y + v[i].z + v[i].w;
        s2 += v[i].x * v[i].x + v[i].y * v[i].y + v[i].z * v[i].z + v[i].w * v[i].w;
    }
#pragma unroll
    for (int o = 16; o; o >>= 1) {
        s  += __shfl_xor_sync(0xffffffffu, s, o);
        s2 += __shfl_xor_sync(0xffffffffu, s2, o);
    }
    float mu  = s * (1.0f / MODEL_DIM);
    float var = s2 * (1.0f / MODEL_DIM) - mu * mu;
    float rs  = rsqrtf(var + LN_EPS);
#pragma unroll
    for (int i = 0; i < 2; i++) {
        int c0 = (lane + i * 32) * 4;
        float y[4] = {v[i].x, v[i].y, v[i].z, v[i].w};
#pragma unroll
        for (int j = 0; j < 4; j++)
            y[j] = (y[j] - mu) * rs * gamma[c0 + j] + beta[c0 + j];
        size_t o0 = (size_t)row * MODEL_DIM + c0;
        *(__half2*)(g_xf + o0)     = __half2(__float2half(y[0]), __float2half(y[1]));
        *(__half2*)(g_xf + o0 + 2) = __half2(__float2half(y[2]), __float2half(y[3]));
    }
}

// ------------------------------------------------------------------
// fp32 -> single fp16 conversion (weights)
// ------------------------------------------------------------------
__global__ __launch_bounds__(256) void convf16_kernel(const float* __restrict__ src,
                                                      __half* __restrict__ dst, int n4) {
    int i = blockIdx.x * blockDim.x + threadIdx.x;
    if (i >= n4) return;
    float4 v = ((const float4*)src)[i];
    size_t o0 = (size_t)i * 4;
    *(__half2*)(dst + o0)     = __half2(__float2half(v.x), __float2half(v.y));
    *(__half2*)(dst + o0 + 2) = __half2(__float2half(v.z), __float2half(v.w));
}

// ------------------------------------------------------------------
// K2/K5: HMMA fp16 1-term GEMM, 2-stage cp.async pipeline.
// C[M,N] = Af[M,256] * Bf[N,256]^T, fp32 accum.
// QKV_EPI=0: write fp32 C. QKV_EPI=1: SCALE (cols<256) + rotary via
// table (q cols<32, k cols 256..287), write split-bf16 Chi/Clo.
// Tile 128x128, 256 thr = 8 warps (4m x 2n); K chunks of 32.
// ------------------------------------------------------------------
#define KCH       32
#define NCHUNK    8
#define PITCH     40
#define BUF_B     (128 * PITCH * 2)      /* 10240 B */
#define STAGE_B   (2 * BUF_B)            /* 20480 B: Af, Bf */
#define GSM_TOTAL (2 * STAGE_B)          /* 40960 B */

template <int QKV_EPI>
__global__ __launch_bounds__(256) void mma_gemm_kernel(
    const __half* __restrict__ Af, const __half* __restrict__ Bf,
    float* __restrict__ C, __nv_bfloat16* __restrict__ Chi,
    __nv_bfloat16* __restrict__ Clo, int N) {
    extern __shared__ char smem[];
    uint32_t sbase = smem_u32(smem);
    int tid  = threadIdx.x;
    int lane = tid & 31;
    int wid  = tid >> 5;
    int wm   = wid >> 1;
    int wn   = wid & 1;
    int m0   = blockIdx.y * 128;
    int n0   = blockIdx.x * 128;

    float acc[2][8][4];
#pragma unroll
    for (int mt = 0; mt < 2; mt++)
#pragma unroll
        for (int nt = 0; nt < 8; nt++)
#pragma unroll
            for (int j = 0; j < 4; j++) acc[mt][nt][j] = 0.f;

    const uint4* gsrc[2] = {
        (const uint4*)(Af + (size_t)m0 * MODEL_DIM),
        (const uint4*)(Bf + (size_t)n0 * MODEL_DIM)};

    // loader: chunk ch -> stage st. 2 buffers x 512 x 16B = 4 per thread.
#define LOAD_CHUNK(ch, st)                                                        \
    do {                                                                          \
        uint32_t stb = sbase + (st) * STAGE_B;                                    \
        _Pragma("unroll")                                                         \
        for (int it = 0; it < 4; it++) {                                          \
            int idx = it * 256 + tid;                                             \
            int b = idx >> 9, r = (idx >> 2) & 127, c = idx & 3;                  \
            CP_ASYNC16(stb + b * BUF_B + r * (PITCH * 2) + c * 16,                \
                       (const void*)(gsrc[b] + (ch) * 4 + (size_t)r * 32 + c));   \
        }                                                                         \
        CP_COMMIT();                                                              \
    } while (0)

    int a_row_l = lane & 15;
    int a_col_l = (lane >> 4) << 3;
    int b_row_l = (lane & 7) + ((lane >> 4) & 1) * 8;
    int b_col_l = ((lane >> 3) & 1) << 3;

    LOAD_CHUNK(0, 0);

    for (int ch = 0; ch < NCHUNK; ch++) {
        int st = ch & 1;
        if (ch + 1 < NCHUNK) {
            LOAD_CHUNK(ch + 1, st ^ 1);
            CP_WAIT(1);
        } else {
            CP_WAIT(0);
        }
        __syncthreads();

        uint32_t sA = sbase + st * STAGE_B;
        uint32_t sB = sA + BUF_B;

#pragma unroll
        for (int ks = 0; ks < 2; ks++) {
            int k = ks * 16;
            uint32_t af[2][4], bf[8][2];
#pragma unroll
            for (int mt = 0; mt < 2; mt++) {
                uint32_t off = (uint32_t)((wm * 32 + mt * 16 + a_row_l) * (PITCH * 2) +
                                          (k + a_col_l) * 2);
                LDMATRIX_X4(af[mt][0], af[mt][1], af[mt][2], af[mt][3], sA + off);
            }
#pragma unroll
            for (int p = 0; p < 4; p++) {
                uint32_t off = (uint32_t)((wn * 64 + p * 16 + b_row_l) * (PITCH * 2) +
                                          (k + b_col_l) * 2);
                LDMATRIX_X4(bf[2 * p][0], bf[2 * p][1], bf[2 * p + 1][0], bf[2 * p + 1][1],
                            sB + off);
            }
#pragma unroll
            for (int mt = 0; mt < 2; mt++)
#pragma unroll
                for (int nt = 0; nt < 8; nt++)
                    MMA_F16(acc[mt][nt], af[mt], bf[nt]);
        }
        __syncthreads();
    }
#undef LOAD_CHUNK

    int gid  = lane >> 2;
    int tq   = lane & 3;
    if (QKV_EPI == 0) {
#pragma unroll
        for (int mt = 0; mt < 2; mt++) {
            int row = m0 + wm * 32 + mt * 16 + gid;
#pragma unroll
            for (int nt = 0; nt < 8; nt++) {
                int col = n0 + wn * 64 + nt * 8 + tq * 2;
                *(float2*)(C + (size_t)row * N + col)       = make_float2(acc[mt][nt][0], acc[mt][nt][1]);
                *(float2*)(C + (size_t)(row + 8) * N + col) = make_float2(acc[mt][nt][2], acc[mt][nt][3]);
            }
        }
    } else {
        int xco = (m0 >> 7) & 127;  // rows in this tile share x; y = row & 127
#pragma unroll
        for (int mt = 0; mt < 2; mt++) {
            int r0 = m0 + wm * 32 + mt * 16 + gid;
            int y0 = r0 & 127;
#pragma unroll
            for (int nt = 0; nt < 8; nt++) {
                int cg = n0 + wn * 64 + nt * 8 + tq * 2;
                float v0 = acc[mt][nt][0], v1 = acc[mt][nt][1];
                float v2 = acc[mt][nt][2], v3 = acc[mt][nt][3];
                int pi = -1;
                if (cg < 256) {
                    v0 *= SCALE; v1 *= SCALE; v2 *= SCALE; v3 *= SCALE;
                    if (cg < 32) pi = cg >> 1;
                } else if (cg < 288) {
                    pi = (cg - 256) >> 1;
                }
                if (pi >= 0) {
                    int i0 = pi * 128 + ((pi < 8) ? xco : y0);
                    int i1 = pi * 128 + ((pi < 8) ? xco : y0 + 8);
                    float c0 = g_rotc[i0], s0 = g_rots[i0];
                    float c1 = g_rotc[i1], s1 = g_rots[i1];
                    float n0f = v0 * c0 - v1 * s0;
                    v1 = v1 * c0 + v0 * s0; v0 = n0f;
                    float n2f = v2 * c1 - v3 * s1;
                    v3 = v3 * c1 + v2 * s1; v2 = n2f;
                }
                size_t off0 = (size_t)r0 * N + cg;
                size_t off1 = (size_t)(r0 + 8) * N + cg;
                __nv_bfloat16 h0 = __float2bfloat16(v0), h1 = __float2bfloat16(v1);
                __nv_bfloat16 h2 = __float2bfloat16(v2), h3 = __float2bfloat16(v3);
                *(__nv_bfloat162*)(Chi + off0) = __nv_bfloat162(h0, h1);
                *(__nv_bfloat162*)(Chi + off1) = __nv_bfloat162(h2, h3);
                *(__nv_bfloat162*)(Clo + off0) =
                    __nv_bfloat162(__float2bfloat16(v0 - __bfloat162float(h0)),
                                   __float2bfloat16(v1 - __bfloat162float(h1)));
                *(__nv_bfloat162*)(Clo + off1) =
                    __nv_bfloat162(__float2bfloat16(v2 - __bfloat162float(h2)),
                                   __float2bfloat16(v3 - __bfloat162float(h3)));
            }
        }
    }
}

// ------------------------------------------------------------------
// K4: tensorized attention per (b,x,h). 128 threads (4 warps).
// q pre-scaled + rotary applied upstream; loader = pure cp.async.
// S = Q K^T 3-term bf16 HMMA; register softmax; O = P V 3-term.
// Emits single fp16 to g_of for the fp16 out-GEMM.
// ------------------------------------------------------------------
#define APITCH    40
#define ATILE_B   (128 * APITCH * 2)
#define ASM_TOTAL (6 * ATILE_B + 512)

__global__ __launch_bounds__(128) void attn_mma_kernel(const void* __restrict__ mask_raw) {
    extern __shared__ char asmem[];
    uint32_t sb   = smem_u32(asmem);
    uint32_t sQhi = sb;
    uint32_t sQlo = sb + ATILE_B;
    uint32_t sKhi = sb + 2 * ATILE_B;
    uint32_t sKlo = sb + 3 * ATILE_B;
    uint32_t sVhi = sb + 4 * ATILE_B;
    uint32_t sVlo = sb + 5 * ATILE_B;
    float*   Mb   = (float*)(asmem + 6 * ATILE_B);

    int h    = blockIdx.x & 7;
    int bx   = blockIdx.x >> 3;
    int tid  = threadIdx.x;
    int lane = tid & 31;
    int w    = tid >> 5;
    size_t base = (size_t)bx * 128;

    {
#pragma unroll
        for (int it = 0; it < 24; it++) {
            int idx  = it * 128 + tid;
            int tile = idx >> 9;
            int r    = (idx >> 2) & 127;
            int chn  = idx & 3;
            const __nv_bfloat16* srcb = (tile & 1) ? g_qkvlo : g_qkvhi;
            const char* src = (const char*)(srcb + (base + r) * QKV_DIM +
                                            (tile >> 1) * 256 + h * HEAD_DIM) + chn * 16;
            CP_ASYNC16(sb + tile * ATILE_B + r * (APITCH * 2) + chn * 16, src);
        }
        CP_COMMIT();
        size_t mi = base + tid;
        unsigned mv = g_mask_is_u8 ? (unsigned)((const unsigned char*)mask_raw)[mi]
                                   : ((const unsigned int*)mask_raw)[mi];
        Mb[tid] = (mv != 0u) ? 1.0f : 0.0f;
        CP_WAIT(0);
    }
    __syncthreads();

    uint32_t aQhi[2][2][4], aQlo[2][2][4];
#pragma unroll
    for (int mt = 0; mt < 2; mt++)
#pragma unroll
        for (int ks = 0; ks < 2; ks++) {
            uint32_t off = (uint32_t)((w * 32 + mt * 16 + (lane & 15)) * (APITCH * 2) +
                                      (ks * 16 + ((lane >> 4) << 3)) * 2);
            LDMATRIX_X4(aQhi[mt][ks][0], aQhi[mt][ks][1], aQhi[mt][ks][2], aQhi[mt][ks][3],
                        sQhi + off);
            LDMATRIX_X4(aQlo[mt][ks][0], aQlo[mt][ks][1], aQlo[mt][ks][2], aQlo[mt][ks][3],
                        sQlo + off);
        }

    float c[2][16][4];
#pragma unroll
    for (int mt = 0; mt < 2; mt++)
#pragma unroll
        for (int nt = 0; nt < 16; nt++)
#pragma unroll
            for (int j = 0; j < 4; j++) c[mt][nt][j] = 0.f;

    int kb_row = (lane & 7) + ((lane >> 4) & 1) * 8;
    int kb_col = ((lane >> 3) & 1) << 3;
#pragma unroll
    for (int t = 0; t < 3; t++) {
        uint32_t sK = (t == 1) ? sKlo : sKhi;
#pragma unroll
        for (int ks = 0; ks < 2; ks++) {
            uint32_t bK[16][2];
#pragma unroll
            for (int p = 0; p < 8; p++) {
                uint32_t off = (uint32_t)((p * 16 + kb_row) * (APITCH * 2) +
                                          (ks * 16 + kb_col) * 2);
                LDMATRIX_X4(bK[2 * p][0], bK[2 * p][1], bK[2 * p + 1][0], bK[2 * p + 1][1],
                            sK + off);
            }
#pragma unroll
            for (int mt = 0; mt < 2; mt++) {
                const uint32_t* A = (t == 2) ? aQlo[mt][ks] : aQhi[mt][ks];
#pragma unroll
                for (int nt = 0; nt < 16; nt++) MMA_BF16(c[mt][nt], A, bK[nt]);
            }
        }
    }

#pragma unroll
    for (int mt = 0; mt < 2; mt++) {
        float m0 = -3.0e38f, m1 = -3.0e38f;
#pragma unroll
        for (int nt = 0; nt < 16; nt++) {
#pragma unroll
            for (int jc = 0; jc < 2; jc++) {
                int col = nt * 8 + (lane & 3) * 2 + jc;
                bool mk = (Mb[col] != 0.f);
                float v0 = mk ? MASK_BIAS : c[mt][nt][jc];
                float v1 = mk ? MASK_BIAS : c[mt][nt][jc + 2];
                c[mt][nt][jc]     = v0;
                c[mt][nt][jc + 2] = v1;
                m0 = fmaxf(m0, v0);
                m1 = fmaxf(m1, v1);
            }
        }
        m0 = fmaxf(m0, __shfl_xor_sync(0xffffffffu, m0, 1));
        m0 = fmaxf(m0, __shfl_xor_sync(0xffffffffu, m0, 2));
        m1 = fmaxf(m1, __shfl_xor_sync(0xffffffffu, m1, 1));
        m1 = fmaxf(m1, __shfl_xor_sync(0xffffffffu, m1, 2));
        float s0 = 0.f, s1 = 0.f;
#pragma unroll
        for (int nt = 0; nt < 16; nt++) {
#pragma unroll
            for (int jc = 0; jc < 2; jc++) {
                float p0 = __expf(c[mt][nt][jc] - m0);
                float p1 = __expf(c[mt][nt][jc + 2] - m1);
                c[mt][nt][jc]     = p0;
                c[mt][nt][jc + 2] = p1;
                s0 += p0;
                s1 += p1;
            }
        }
        s0 += __shfl_xor_sync(0xffffffffu, s0, 1);
        s0 += __shfl_xor_sync(0xffffffffu, s0, 2);
        s1 += __shfl_xor_sync(0xffffffffu, s1, 1);
        s1 += __shfl_xor_sync(0xffffffffu, s1, 2);
        float i0 = 1.0f / s0, i1 = 1.0f / s1;
#pragma unroll
        for (int nt = 0; nt < 16; nt++) {
            c[mt][nt][0] *= i0;
            c[mt][nt][1] *= i0;
            c[mt][nt][2] *= i1;
            c[mt][nt][3] *= i1;
        }
    }

    float o[2][4][4];
#pragma unroll
    for (int mt = 0; mt < 2; mt++)
#pragma unroll
        for (int nt = 0; nt < 4; nt++)
#pragma unroll
            for (int j = 0; j < 4; j++) o[mt][nt][j] = 0.f;

    int vb_row = (lane & 7) + ((lane >> 3) & 1) * 8;
    int vb_col = (lane >> 4) << 3;
#pragma unroll
    for (int ks = 0; ks < 8; ks++) {
        uint32_t bVhi[4][2], bVlo[4][2];
#pragma unroll
        for (int nb = 0; nb < 2; nb++) {
            uint32_t off = (uint32_t)((ks * 16 + vb_row) * (APITCH * 2) +
                                      (nb * 16 + vb_col) * 2);
            LDMATRIX_X4_T(bVhi[2 * nb][0], bVhi[2 * nb][1], bVhi[2 * nb + 1][0],
                          bVhi[2 * nb + 1][1], sVhi + off);
            LDMATRIX_X4_T(bVlo[2 * nb][0], bVlo[2 * nb][1], bVlo[2 * nb + 1][0],
                          bVlo[2 * nb + 1][1], sVlo + off);
        }
#pragma unroll
        for (int mt = 0; mt < 2; mt++) {
            uint32_t phi[4], plo[4];
#pragma unroll
            for (int half = 0; half < 2; half++) {
                const float* cc = c[mt][2 * ks + half];
#pragma unroll
                for (int pr = 0; pr < 2; pr++) {
                    float p0 = cc[pr * 2], p1 = cc[pr * 2 + 1];
                    __nv_bfloat16 h0 = __float2bfloat16(p0), h1 = __float2bfloat16(p1);
                    __nv_bfloat162 hp(h0, h1);
                    phi[half * 2 + pr] = *(uint32_t*)&hp;
                    __nv_bfloat162 lp(__float2bfloat16(p0 - __bfloat162float(h0)),
                                      __float2bfloat16(p1 - __bfloat162float(h1)));
                    plo[half * 2 + pr] = *(uint32_t*)&lp;
                }
            }
#pragma unroll
            for (int nt = 0; nt < 4; nt++) {
                MMA_BF16(o[mt][nt], phi, bVhi[nt]);
                MMA_BF16(o[mt][nt], phi, bVlo[nt]);
                MMA_BF16(o[mt][nt], plo, bVhi[nt]);
            }
        }
    }

    // epilogue: single-fp16 store for the fp16 out-GEMM
    int gid = lane >> 2, tq = lane & 3;
#pragma unroll
    for (int mt = 0; mt < 2; mt++) {
        int row0 = w * 32 + mt * 16 + gid;
#pragma unroll
        for (int nt = 0; nt < 4; nt++) {
            int col = h * 32 + nt * 8 + tq * 2;
            size_t off0 = (base + row0) * MODEL_DIM + col;
            size_t off1 = (base + row0 + 8) * MODEL_DIM + col;
            *(__half2*)(g_of + off0) = __half2(__float2half(o[mt][nt][0]),
                                               __float2half(o[mt][nt][1]));
            *(__half2*)(g_of + off1) = __half2(__float2half(o[mt][nt][2]),
                                               __float2half(o[mt][nt][3]));
        }
    }
}

// ------------------------------------------------------------------
extern "C" void kernel_launch(void* const* d_in, const int* in_sizes, int n_in,
                              void* d_out, int out_size) {
    const float* pair_act  = (const float*)d_in[0];
    const void*  pair_mask = (const void*)d_in[1];
    const float* ln_gamma  = (const float*)d_in[2];
    const float* ln_beta   = (const float*)d_in[3];
    const float* Wqkv      = (const float*)d_in[4];
    const float* Wout      = (const float*)d_in[5];
    float*       out       = (float*)d_out;

    (void)in_sizes; (void)n_in; (void)out_size;

    cudaFuncSetAttribute(mma_gemm_kernel<0>, cudaFuncAttributeMaxDynamicSharedMemorySize, GSM_TOTAL);
    cudaFuncSetAttribute(mma_gemm_kernel<1>, cudaFuncAttributeMaxDynamicSharedMemorySize, GSM_TOTAL);
    cudaFuncSetAttribute(attn_mma_kernel, cudaFuncAttributeMaxDynamicSharedMemorySize, ASM_TOTAL);

    __half *xf, *of, *wf, *wof;
    __nv_bfloat16 *qhi, *qlo;
    cudaGetSymbolAddress((void**)&xf, g_xf);
    cudaGetSymbolAddress((void**)&of, g_of);
    cudaGetSymbolAddress((void**)&wf, g_wf);
    cudaGetSymbolAddress((void**)&wof, g_wof);
    cudaGetSymbolAddress((void**)&qhi, g_qkvhi);
    cudaGetSymbolAddress((void**)&qlo, g_qkvlo);

    mask_detect_kernel<<<1, 256>>>((const unsigned char*)pair_mask);
    rot_fill_kernel<<<8, 256>>>();
    ln_conv_kernel<<<ROWS / 8, dim3(32, 8)>>>(pair_act, ln_gamma, ln_beta);
    convf16_kernel<<<(QKV_DIM * MODEL_DIM / 4 + 255) / 256, 256>>>(Wqkv, wf, QKV_DIM * MODEL_DIM / 4);
    convf16_kernel<<<(MODEL_DIM * MODEL_DIM / 4 + 255) / 256, 256>>>(Wout, wof, MODEL_DIM * MODEL_DIM / 4);

    mma_gemm_kernel<1><<<dim3(QKV_DIM / 128, ROWS / 128), 256, GSM_TOTAL>>>(
        xf, wf, nullptr, qhi, qlo, QKV_DIM);

    attn_mma_kernel<<<BATCH * SEQ * NUM_HEAD, 128, ASM_TOTAL>>>(pair_mask);

    mma_gemm_kernel<0><<<dim3(MODEL_DIM / 128, ROWS / 128), 256, GSM_TOTAL>>>(
        of, wof, out, nullptr, nullptr, MODEL_DIM);
}

// round 16
// speedup vs baseline: 1.8107x; 1.1746x over previous
#include <cuda_runtime.h>
#include <cuda_bf16.h>
#include <cuda_fp16.h>
#include <math.h>
#include <stdint.h>

#define MODEL_DIM 256
#define NUM_HEAD  8
#define HEAD_DIM  32
#define SEQ       128
#define BATCH     2
#define ROWS      (BATCH * SEQ * SEQ)   /* 32768 */
#define QKV_DIM   768
#define SCALE     0.17677669529663687f  /* 32^-0.5 */
#define LN_EPS    1e-5f
#define MASK_BIAS -1000000000.0f
#define MASK_N    (BATCH * SEQ * SEQ)

// -------- scratch (static device globals; no runtime allocation) --------
__device__ __half g_qhi[(size_t)ROWS * MODEL_DIM];   // q fp16 hi (scaled+rotary)
__device__ __half g_qlo[(size_t)ROWS * MODEL_DIM];   // q fp16 lo
__device__ __half g_kvf[(size_t)ROWS * 512];         // k (cols 0..255, rotary) | v (256..511)
__device__ __half g_xf[(size_t)ROWS * MODEL_DIM];    // LN(x) fp16
__device__ __half g_of[(size_t)ROWS * MODEL_DIM];    // attn out fp16
__device__ __half g_wf[QKV_DIM * MODEL_DIM];         // Wqkv fp16
__device__ __half g_wof[MODEL_DIM * MODEL_DIM];      // Wout fp16
__device__ float  g_rotc[16 * 128];
__device__ float  g_rots[16 * 128];
__device__ unsigned g_mask_is_u8;

__device__ __forceinline__ uint32_t smem_u32(const void* p) {
    uint32_t a;
    asm("{ .reg .u64 t; cvta.to.shared.u64 t, %1; cvt.u32.u64 %0, t; }" : "=r"(a) : "l"(p));
    return a;
}

#define CP_ASYNC16(saddr, gptr) \
    asm volatile("cp.async.cg.shared.global [%0], [%1], 16;" :: "r"(saddr), "l"(gptr))
#define CP_COMMIT() asm volatile("cp.async.commit_group;" ::: "memory")
#define CP_WAIT(n)  asm volatile("cp.async.wait_group %0;" :: "n"(n) : "memory")

#define LDMATRIX_X4(r0, r1, r2, r3, addr) \
    asm volatile("ldmatrix.sync.aligned.m8n8.x4.shared.b16 {%0,%1,%2,%3}, [%4];" \
                 : "=r"(r0), "=r"(r1), "=r"(r2), "=r"(r3) : "r"(addr))

#define LDMATRIX_X4_T(r0, r1, r2, r3, addr) \
    asm volatile("ldmatrix.sync.aligned.m8n8.x4.trans.shared.b16 {%0,%1,%2,%3}, [%4];" \
                 : "=r"(r0), "=r"(r1), "=r"(r2), "=r"(r3) : "r"(addr))

#define MMA_F16(d, a, b) \
    asm volatile("mma.sync.aligned.m16n8k16.row.col.f32.f16.f16.f32 " \
                 "{%0,%1,%2,%3}, {%4,%5,%6,%7}, {%8,%9}, {%0,%1,%2,%3};" \
                 : "+f"((d)[0]), "+f"((d)[1]), "+f"((d)[2]), "+f"((d)[3]) \
                 : "r"((a)[0]), "r"((a)[1]), "r"((a)[2]), "r"((a)[3]), \
                   "r"((b)[0]), "r"((b)[1]))

// ------------------------------------------------------------------
// K0a: detect mask element width (word widenings of 0/1 have byte i%4==1 zero)
// ------------------------------------------------------------------
__global__ void mask_detect_kernel(const unsigned char* __restrict__ m) {
    __shared__ int any;
    if (threadIdx.x == 0) any = 0;
    __syncthreads();
    int found = 0;
    for (int i = threadIdx.x; i < MASK_N / 4; i += blockDim.x)
        if (m[i * 4 + 1]) found = 1;
    if (found) atomicOr(&any, 1);
    __syncthreads();
    if (threadIdx.x == 0) g_mask_is_u8 = (unsigned)any;
}

// ------------------------------------------------------------------
// K0b: fill rotary cos/sin table: index = pi*128 + pos, pi in [0,16)
// ------------------------------------------------------------------
__global__ void rot_fill_kernel() {
    int i   = blockIdx.x * 256 + threadIdx.x;  // 0..2047
    int pi  = i >> 7;
    int pos = i & 127;
    float invf = exp2f(-(float)(pi & 7) * 1.6609640474436813f);
    float t    = (float)pos * (2.0f / 127.0f) - 1.0f;
    float f    = t * invf;
    g_rotc[i] = cosf(f);
    g_rots[i] = sinf(f);
}

// ------------------------------------------------------------------
// K1: fused LayerNorm + fp16 conversion. One warp per row of 256.
// ------------------------------------------------------------------
__global__ __launch_bounds__(256) void ln_conv_kernel(const float* __restrict__ x,
                                                      const float* __restrict__ gamma,
                                                      const float* __restrict__ beta) {
    int row  = blockIdx.x * 8 + threadIdx.y;
    int lane = threadIdx.x;
    const float* xr = x + (size_t)row * MODEL_DIM;
    float4 v[2];
    float s = 0.f, s2 = 0.f;
#pragma unroll
    for (int i = 0; i < 2; i++) {
        v[i] = reinterpret_cast<const float4*>(xr)[lane + i * 32];
        s  += v[i].x + v[i].y + v[i].z + v[i].w;
        s2 += v[i].x * v[i].x + v[i].y * v[i].y + v[i].z * v[i].z + v[i].w * v[i].w;
    }
#pragma unroll
    for (int o = 16; o; o >>= 1) {
        s  += __shfl_xor_sync(0xffffffffu, s, o);
        s2 += __shfl_xor_sync(0xffffffffu, s2, o);
    }
    float mu  = s * (1.0f / MODEL_DIM);
    float var = s2 * (1.0f / MODEL_DIM) - mu * mu;
    float rs  = rsqrtf(var + LN_EPS);
#pragma unroll
    for (int i = 0; i < 2; i++) {
        int c0 = (lane + i * 32) * 4;
        float y[4] = {v[i].x, v[i].y, v[i].z, v[i].w};
#pragma unroll
        for (int j = 0; j < 4; j++)
            y[j] = (y[j] - mu) * rs * gamma[c0 + j] + beta[c0 + j];
        size_t o0 = (size_t)row * MODEL_DIM + c0;
        *(__half2*)(g_xf + o0)     = __half2(__float2half(y[0]), __float2half(y[1]));
        *(__half2*)(g_xf + o0 + 2) = __half2(__float2half(y[2]), __float2half(y[3]));
    }
}

// ------------------------------------------------------------------
// fp32 -> single fp16 conversion (weights)
// ------------------------------------------------------------------
__global__ __launch_bounds__(256) void convf16_kernel(const float* __restrict__ src,
                                                      __half* __restrict__ dst, int n4) {
    int i = blockIdx.x * blockDim.x + threadIdx.x;
    if (i >= n4) return;
    float4 v = ((const float4*)src)[i];
    size_t o0 = (size_t)i * 4;
    *(__half2*)(dst + o0)     = __half2(__float2half(v.x), __float2half(v.y));
    *(__half2*)(dst + o0 + 2) = __half2(__float2half(v.z), __float2half(v.w));
}

// ------------------------------------------------------------------
// K2/K5: HMMA fp16 1-term GEMM, 2-stage cp.async pipeline.
// C[M,N] = Af[M,256] * Bf[N,256]^T, fp32 accum.
// QKV_EPI=0: write fp32 C.
// QKV_EPI=1: q cols (<256): SCALE + rotary(<32) -> g_qhi/g_qlo split;
//            k cols (256..511): rotary(<288) -> g_kvf[0..255] fp16;
//            v cols (512..767): -> g_kvf[256..511] fp16.
// ------------------------------------------------------------------
#define KCH       32
#define NCHUNK    8
#define PITCH     40
#define BUF_B     (128 * PITCH * 2)      /* 10240 B */
#define STAGE_B   (2 * BUF_B)            /* 20480 B: Af, Bf */
#define GSM_TOTAL (2 * STAGE_B)          /* 40960 B */

template <int QKV_EPI>
__global__ __launch_bounds__(256) void mma_gemm_kernel(
    const __half* __restrict__ Af, const __half* __restrict__ Bf,
    float* __restrict__ C, int N) {
    extern __shared__ char smem[];
    uint32_t sbase = smem_u32(smem);
    int tid  = threadIdx.x;
    int lane = tid & 31;
    int wid  = tid >> 5;
    int wm   = wid >> 1;
    int wn   = wid & 1;
    int m0   = blockIdx.y * 128;
    int n0   = blockIdx.x * 128;

    float acc[2][8][4];
#pragma unroll
    for (int mt = 0; mt < 2; mt++)
#pragma unroll
        for (int nt = 0; nt < 8; nt++)
#pragma unroll
            for (int j = 0; j < 4; j++) acc[mt][nt][j] = 0.f;

    const uint4* gsrc[2] = {
        (const uint4*)(Af + (size_t)m0 * MODEL_DIM),
        (const uint4*)(Bf + (size_t)n0 * MODEL_DIM)};

#define LOAD_CHUNK(ch, st)                                                        \
    do {                                                                          \
        uint32_t stb = sbase + (st) * STAGE_B;                                    \
        _Pragma("unroll")                                                         \
        for (int it = 0; it < 4; it++) {                                          \
            int idx = it * 256 + tid;                                             \
            int b = idx >> 9, r = (idx >> 2) & 127, c = idx & 3;                  \
            CP_ASYNC16(stb + b * BUF_B + r * (PITCH * 2) + c * 16,                \
                       (const void*)(gsrc[b] + (ch) * 4 + (size_t)r * 32 + c));   \
        }                                                                         \
        CP_COMMIT();                                                              \
    } while (0)

    int a_row_l = lane & 15;
    int a_col_l = (lane >> 4) << 3;
    int b_row_l = (lane & 7) + ((lane >> 4) & 1) * 8;
    int b_col_l = ((lane >> 3) & 1) << 3;

    LOAD_CHUNK(0, 0);

    for (int ch = 0; ch < NCHUNK; ch++) {
        int st = ch & 1;
        if (ch + 1 < NCHUNK) {
            LOAD_CHUNK(ch + 1, st ^ 1);
            CP_WAIT(1);
        } else {
            CP_WAIT(0);
        }
        __syncthreads();

        uint32_t sA = sbase + st * STAGE_B;
        uint32_t sB = sA + BUF_B;

#pragma unroll
        for (int ks = 0; ks < 2; ks++) {
            int k = ks * 16;
            uint32_t af[2][4], bf[8][2];
#pragma unroll
            for (int mt = 0; mt < 2; mt++) {
                uint32_t off = (uint32_t)((wm * 32 + mt * 16 + a_row_l) * (PITCH * 2) +
                                          (k + a_col_l) * 2);
                LDMATRIX_X4(af[mt][0], af[mt][1], af[mt][2], af[mt][3], sA + off);
            }
#pragma unroll
            for (int p = 0; p < 4; p++) {
                uint32_t off = (uint32_t)((wn * 64 + p * 16 + b_row_l) * (PITCH * 2) +
                                          (k + b_col_l) * 2);
                LDMATRIX_X4(bf[2 * p][0], bf[2 * p][1], bf[2 * p + 1][0], bf[2 * p + 1][1],
                            sB + off);
            }
#pragma unroll
            for (int mt = 0; mt < 2; mt++)
#pragma unroll
                for (int nt = 0; nt < 8; nt++)
                    MMA_F16(acc[mt][nt], af[mt], bf[nt]);
        }
        __syncthreads();
    }
#undef LOAD_CHUNK

    int gid  = lane >> 2;
    int tq   = lane & 3;
    if (QKV_EPI == 0) {
#pragma unroll
        for (int mt = 0; mt < 2; mt++) {
            int row = m0 + wm * 32 + mt * 16 + gid;
#pragma unroll
            for (int nt = 0; nt < 8; nt++) {
                int col = n0 + wn * 64 + nt * 8 + tq * 2;
                *(float2*)(C + (size_t)row * N + col)       = make_float2(acc[mt][nt][0], acc[mt][nt][1]);
                *(float2*)(C + (size_t)(row + 8) * N + col) = make_float2(acc[mt][nt][2], acc[mt][nt][3]);
            }
        }
    } else {
        int xco = (m0 >> 7) & 127;  // rows in this tile share x; y = row & 127
#pragma unroll
        for (int mt = 0; mt < 2; mt++) {
            int r0 = m0 + wm * 32 + mt * 16 + gid;
            int y0 = r0 & 127;
#pragma unroll
            for (int nt = 0; nt < 8; nt++) {
                int cg = n0 + wn * 64 + nt * 8 + tq * 2;
                float v0 = acc[mt][nt][0], v1 = acc[mt][nt][1];
                float v2 = acc[mt][nt][2], v3 = acc[mt][nt][3];
                int pi = -1;
                if (cg < 256) {
                    v0 *= SCALE; v1 *= SCALE; v2 *= SCALE; v3 *= SCALE;
                    if (cg < 32) pi = cg >> 1;
                } else if (cg < 288) {
                    pi = (cg - 256) >> 1;
                }
                if (pi >= 0) {
                    int i0 = pi * 128 + ((pi < 8) ? xco : y0);
                    int i1 = pi * 128 + ((pi < 8) ? xco : y0 + 8);
                    float c0 = g_rotc[i0], s0 = g_rots[i0];
                    float c1 = g_rotc[i1], s1 = g_rots[i1];
                    float n0f = v0 * c0 - v1 * s0;
                    v1 = v1 * c0 + v0 * s0; v0 = n0f;
                    float n2f = v2 * c1 - v3 * s1;
                    v3 = v3 * c1 + v2 * s1; v2 = n2f;
                }
                __half h0 = __float2half(v0), h1 = __float2half(v1);
                __half h2 = __float2half(v2), h3 = __float2half(v3);
                if (cg < 256) {
                    size_t off0 = (size_t)r0 * MODEL_DIM + cg;
                    size_t off1 = (size_t)(r0 + 8) * MODEL_DIM + cg;
                    *(__half2*)(g_qhi + off0) = __half2(h0, h1);
                    *(__half2*)(g_qhi + off1) = __half2(h2, h3);
                    *(__half2*)(g_qlo + off0) =
                        __half2(__float2half(v0 - __half2float(h0)),
                                __float2half(v1 - __half2float(h1)));
                    *(__half2*)(g_qlo + off1) =
                        __half2(__float2half(v2 - __half2float(h2)),
                                __float2half(v3 - __half2float(h3)));
                } else {
                    int kc = cg - 256;  // k: [0,256), v: [256,512)
                    size_t off0 = (size_t)r0 * 512 + kc;
                    size_t off1 = (size_t)(r0 + 8) * 512 + kc;
                    *(__half2*)(g_kvf + off0) = __half2(h0, h1);
                    *(__half2*)(g_kvf + off1) = __half2(h2, h3);
                }
            }
        }
    }
}

// ------------------------------------------------------------------
// K4: tensorized attention per (b,x,h). 128 threads (4 warps).
// q pre-scaled + rotary upstream. 4 smem tiles: Qhi, Qlo, K, V.
// S = (Qhi+Qlo) K^T  (2-term fp16);  O = (Phi+Plo) V  (2-term fp16).
// Emits single fp16 to g_of for the fp16 out-GEMM.
// ------------------------------------------------------------------
#define APITCH    40
#define ATILE_B   (128 * APITCH * 2)
#define ASM_TOTAL (4 * ATILE_B + 512)

__global__ __launch_bounds__(128) void attn_mma_kernel(const void* __restrict__ mask_raw) {
    extern __shared__ char asmem[];
    uint32_t sb   = smem_u32(asmem);
    uint32_t sQhi = sb;
    uint32_t sQlo = sb + ATILE_B;
    uint32_t sK   = sb + 2 * ATILE_B;
    uint32_t sV   = sb + 3 * ATILE_B;
    float*   Mb   = (float*)(asmem + 4 * ATILE_B);

    int h    = blockIdx.x & 7;
    int bx   = blockIdx.x >> 3;
    int tid  = threadIdx.x;
    int lane = tid & 31;
    int w    = tid >> 5;
    size_t base = (size_t)bx * 128;

    // loader: 4 tiles x 128 rows x 64B = 16 cp.async per thread
    {
#pragma unroll
        for (int it = 0; it < 16; it++) {
            int idx  = it * 128 + tid;       // 0..2047
            int tile = idx >> 9;             // 0: Qhi, 1: Qlo, 2: K, 3: V
            int r    = (idx >> 2) & 127;
            int chn  = idx & 3;
            const __half* src;
            if (tile == 0)      src = g_qhi + (base + r) * MODEL_DIM + h * HEAD_DIM;
            else if (tile == 1) src = g_qlo + (base + r) * MODEL_DIM + h * HEAD_DIM;
            else if (tile == 2) src = g_kvf + (base + r) * 512 + h * HEAD_DIM;
            else                src = g_kvf + (base + r) * 512 + 256 + h * HEAD_DIM;
            CP_ASYNC16(sb + tile * ATILE_B + r * (APITCH * 2) + chn * 16,
                       (const char*)src + chn * 16);
        }
        CP_COMMIT();
        size_t mi = base + tid;
        unsigned mv = g_mask_is_u8 ? (unsigned)((const unsigned char*)mask_raw)[mi]
                                   : ((const unsigned int*)mask_raw)[mi];
        Mb[tid] = (mv != 0u) ? 1.0f : 0.0f;
        CP_WAIT(0);
    }
    __syncthreads();

    // ---------------- S = (Qhi+Qlo) K^T ----------------
    uint32_t aQhi[2][2][4], aQlo[2][2][4];
#pragma unroll
    for (int mt = 0; mt < 2; mt++)
#pragma unroll
        for (int ks = 0; ks < 2; ks++) {
            uint32_t off = (uint32_t)((w * 32 + mt * 16 + (lane & 15)) * (APITCH * 2) +
                                      (ks * 16 + ((lane >> 4) << 3)) * 2);
            LDMATRIX_X4(aQhi[mt][ks][0], aQhi[mt][ks][1], aQhi[mt][ks][2], aQhi[mt][ks][3],
                        sQhi + off);
            LDMATRIX_X4(aQlo[mt][ks][0], aQlo[mt][ks][1], aQlo[mt][ks][2], aQlo[mt][ks][3],
                        sQlo + off);
        }

    float c[2][16][4];
#pragma unroll
    for (int mt = 0; mt < 2; mt++)
#pragma unroll
        for (int nt = 0; nt < 16; nt++)
#pragma unroll
            for (int j = 0; j < 4; j++) c[mt][nt][j] = 0.f;

    int kb_row = (lane & 7) + ((lane >> 4) & 1) * 8;
    int kb_col = ((lane >> 3) & 1) << 3;
#pragma unroll
    for (int ks = 0; ks < 2; ks++) {
        uint32_t bK[16][2];
#pragma unroll
        for (int p = 0; p < 8; p++) {
            uint32_t off = (uint32_t)((p * 16 + kb_row) * (APITCH * 2) +
                                      (ks * 16 + kb_col) * 2);
            LDMATRIX_X4(bK[2 * p][0], bK[2 * p][1], bK[2 * p + 1][0], bK[2 * p + 1][1],
                        sK + off);
        }
#pragma unroll
        for (int mt = 0; mt < 2; mt++)
#pragma unroll
            for (int nt = 0; nt < 16; nt++) {
                MMA_F16(c[mt][nt], aQhi[mt][ks], bK[nt]);
                MMA_F16(c[mt][nt], aQlo[mt][ks], bK[nt]);
            }
    }

    // ---------------- mask + softmax ----------------
#pragma unroll
    for (int mt = 0; mt < 2; mt++) {
        float m0 = -3.0e38f, m1 = -3.0e38f;
#pragma unroll
        for (int nt = 0; nt < 16; nt++) {
#pragma unroll
            for (int jc = 0; jc < 2; jc++) {
                int col = nt * 8 + (lane & 3) * 2 + jc;
                bool mk = (Mb[col] != 0.f);
                float v0 = mk ? MASK_BIAS : c[mt][nt][jc];
                float v1 = mk ? MASK_BIAS : c[mt][nt][jc + 2];
                c[mt][nt][jc]     = v0;
                c[mt][nt][jc + 2] = v1;
                m0 = fmaxf(m0, v0);
                m1 = fmaxf(m1, v1);
            }
        }
        m0 = fmaxf(m0, __shfl_xor_sync(0xffffffffu, m0, 1));
        m0 = fmaxf(m0, __shfl_xor_sync(0xffffffffu, m0, 2));
        m1 = fmaxf(m1, __shfl_xor_sync(0xffffffffu, m1, 1));
        m1 = fmaxf(m1, __shfl_xor_sync(0xffffffffu, m1, 2));
        float s0 = 0.f, s1 = 0.f;
#pragma unroll
        for (int nt = 0; nt < 16; nt++) {
#pragma unroll
            for (int jc = 0; jc < 2; jc++) {
                float p0 = __expf(c[mt][nt][jc] - m0);
                float p1 = __expf(c[mt][nt][jc + 2] - m1);
                c[mt][nt][jc]     = p0;
                c[mt][nt][jc + 2] = p1;
                s0 += p0;
                s1 += p1;
            }
        }
        s0 += __shfl_xor_sync(0xffffffffu, s0, 1);
        s0 += __shfl_xor_sync(0xffffffffu, s0, 2);
        s1 += __shfl_xor_sync(0xffffffffu, s1, 1);
        s1 += __shfl_xor_sync(0xffffffffu, s1, 2);
        float i0 = 1.0f / s0, i1 = 1.0f / s1;
#pragma unroll
        for (int nt = 0; nt < 16; nt++) {
            c[mt][nt][0] *= i0;
            c[mt][nt][1] *= i0;
            c[mt][nt][2] *= i1;
            c[mt][nt][3] *= i1;
        }
    }

    // ---------------- O = (Phi+Plo) V ----------------
    float o[2][4][4];
#pragma unroll
    for (int mt = 0; mt < 2; mt++)
#pragma unroll
        for (int nt = 0; nt < 4; nt++)
#pragma unroll
            for (int j = 0; j < 4; j++) o[mt][nt][j] = 0.f;

    int vb_row = (lane & 7) + ((lane >> 3) & 1) * 8;
    int vb_col = (lane >> 4) << 3;
#pragma unroll
    for (int ks = 0; ks < 8; ks++) {
        uint32_t bV[4][2];
#pragma unroll
        for (int nb = 0; nb < 2; nb++) {
            uint32_t off = (uint32_t)((ks * 16 + vb_row) * (APITCH * 2) +
                                      (nb * 16 + vb_col) * 2);
            LDMATRIX_X4_T(bV[2 * nb][0], bV[2 * nb][1], bV[2 * nb + 1][0],
                          bV[2 * nb + 1][1], sV + off);
        }
#pragma unroll
        for (int mt = 0; mt < 2; mt++) {
            uint32_t phi[4], plo[4];
#pragma unroll
            for (int half = 0; half < 2; half++) {
                const float* cc = c[mt][2 * ks + half];
#pragma unroll
                for (int pr = 0; pr < 2; pr++) {
                    float p0 = cc[pr * 2], p1 = cc[pr * 2 + 1];
                    __half h0 = __float2half(p0), h1 = __float2half(p1);
                    __half2 hp(h0, h1);
                    phi[half * 2 + pr] = *(uint32_t*)&hp;
                    __half2 lp(__float2half(p0 - __half2float(h0)),
                               __float2half(p1 - __half2float(h1)));
                    plo[half * 2 + pr] = *(uint32_t*)&lp;
                }
            }
#pragma unroll
            for (int nt = 0; nt < 4; nt++) {
                MMA_F16(o[mt][nt], phi, bV[nt]);
                MMA_F16(o[mt][nt], plo, bV[nt]);
            }
        }
    }

    // epilogue: single-fp16 store for the fp16 out-GEMM
    int gid = lane >> 2, tq = lane & 3;
#pragma unroll
    for (int mt = 0; mt < 2; mt++) {
        int row0 = w * 32 + mt * 16 + gid;
#pragma unroll
        for (int nt = 0; nt < 4; nt++) {
            int col = h * 32 + nt * 8 + tq * 2;
            size_t off0 = (base + row0) * MODEL_DIM + col;
            size_t off1 = (base + row0 + 8) * MODEL_DIM + col;
            *(__half2*)(g_of + off0) = __half2(__float2half(o[mt][nt][0]),
                                               __float2half(o[mt][nt][1]));
            *(__half2*)(g_of + off1) = __half2(__float2half(o[mt][nt][2]),
                                               __float2half(o[mt][nt][3]));
        }
    }
}

// ------------------------------------------------------------------
extern "C" void kernel_launch(void* const* d_in, const int* in_sizes, int n_in,
                              void* d_out, int out_size) {
    const float* pair_act  = (const float*)d_in[0];
    const void*  pair_mask = (const void*)d_in[1];
    const float* ln_gamma  = (const float*)d_in[2];
    const float* ln_beta   = (const float*)d_in[3];
    const float* Wqkv      = (const float*)d_in[4];
    const float* Wout      = (const float*)d_in[5];
    float*       out       = (float*)d_out;

    (void)in_sizes; (void)n_in; (void)out_size;

    cudaFuncSetAttribute(mma_gemm_kernel<0>, cudaFuncAttributeMaxDynamicSharedMemorySize, GSM_TOTAL);
    cudaFuncSetAttribute(mma_gemm_kernel<1>, cudaFuncAttributeMaxDynamicSharedMemorySize, GSM_TOTAL);
    cudaFuncSetAttribute(attn_mma_kernel, cudaFuncAttributeMaxDynamicSharedMemorySize, ASM_TOTAL);

    __half *xf, *of, *wf, *wof;
    cudaGetSymbolAddress((void**)&xf, g_xf);
    cudaGetSymbolAddress((void**)&of, g_of);
    cudaGetSymbolAddress((void**)&wf, g_wf);
    cudaGetSymbolAddress((void**)&wof, g_wof);

    mask_detect_kernel<<<1, 256>>>((const unsigned char*)pair_mask);
    rot_fill_kernel<<<8, 256>>>();
    ln_conv_kernel<<<ROWS / 8, dim3(32, 8)>>>(pair_act, ln_gamma, ln_beta);
    convf16_kernel<<<(QKV_DIM * MODEL_DIM / 4 + 255) / 256, 256>>>(Wqkv, wf, QKV_DIM * MODEL_DIM / 4);
    convf16_kernel<<<(MODEL_DIM * MODEL_DIM / 4 + 255) / 256, 256>>>(Wout, wof, MODEL_DIM * MODEL_DIM / 4);

    mma_gemm_kernel<1><<<dim3(QKV_DIM / 128, ROWS / 128), 256, GSM_TOTAL>>>(
        xf, wf, nullptr, QKV_DIM);

    attn_mma_kernel<<<BATCH * SEQ * NUM_HEAD, 128, ASM_TOTAL>>>(pair_mask);

    mma_gemm_kernel<0><<<dim3(MODEL_DIM / 128, ROWS / 128), 256, GSM_TOTAL>>>(
        of, wof, out, MODEL_DIM);
}